// round 9
// baseline (speedup 1.0000x reference)
#include <cuda_runtime.h>

// ---------------------------------------------------------------------------
// FrameLevelPartFeatureExtractor — TF32 tensor-core (mma.sync m16n8k8) conv
// pipeline. conv1 packed-f32x2; conv2..conv6 implicit GEMM on HMMA with
// 8h x 32w x 32oc block tile (warp = 1 h-row, M=32 x N=32).
// R9 change: __launch_bounds__(256,3) on the MMA kernel -> 3 blocks/SM
// (register-file was capping occupancy at 2 blocks with 128 regs).
// conv2/conv4 fuse the 2x2 maxpool into their epilogue. Intermediates
// tf32-rounded; final layer plain fp32.
// ---------------------------------------------------------------------------

typedef unsigned int uint;
typedef unsigned long long u64;

__device__ __align__(16) float g_bufA[16777216];
__device__ __align__(16) float g_bufB[16777216];
__device__ __align__(16) float g_bufW[138240];   // packed tf32 weights, w2..w6

__device__ __forceinline__ float dlrelu(float v) {
    return v > 0.0f ? v : 0.01f * (0.01f * v);
}
__device__ __forceinline__ float tf32r(float v) {
    uint u; asm("cvt.rna.tf32.f32 %0, %1;" : "=r"(u) : "f"(v));
    return __uint_as_float(u);
}
__device__ __forceinline__ void cp16(unsigned dst, const void* src, int sz) {
    asm volatile("cp.async.cg.shared.global [%0], [%1], 16, %2;\n"
                 :: "r"(dst), "l"(src), "r"(sz));
}
__device__ __forceinline__ void cp4(unsigned dst, const void* src, int sz) {
    asm volatile("cp.async.ca.shared.global [%0], [%1], 4, %2;\n"
                 :: "r"(dst), "l"(src), "r"(sz));
}
__device__ __forceinline__ void cp_commit() {
    asm volatile("cp.async.commit_group;\n" ::);
}
__device__ __forceinline__ void mma_tf32(float* c, uint a0, uint a1, uint a2,
                                         uint a3, uint b0, uint b1) {
    asm volatile(
        "mma.sync.aligned.m16n8k8.row.col.f32.tf32.tf32.f32 "
        "{%0,%1,%2,%3}, {%4,%5,%6,%7}, {%8,%9}, {%0,%1,%2,%3};"
        : "+f"(c[0]), "+f"(c[1]), "+f"(c[2]), "+f"(c[3])
        : "r"(a0), "r"(a1), "r"(a2), "r"(a3), "r"(b0), "r"(b1));
}
__device__ __forceinline__ u64 dup_f(float v) {
    u64 r; asm("mov.b64 %0, {%1, %1};" : "=l"(r) : "f"(v)); return r;
}
__device__ __forceinline__ void ffma2(u64& d, u64 a, u64 b) {
    asm("fma.rn.f32x2 %0, %1, %2, %0;" : "+l"(d) : "l"(a), "l"(b));
}
__device__ __forceinline__ float2 unpk(u64 a) {
    float2 f; asm("mov.b64 {%0, %1}, %2;" : "=f"(f.x), "=f"(f.y) : "l"(a));
    return f;
}

// ---------------------------------------------------------------------------
// Fused weight pack for layers 2..6 (layout unchanged):
// pk[((ocg*NCH + t)*TAPS + tap)*4 + gg][lane][j] =
//   tf32( W[ocg*32 + gg*8 + lane/4][t*8 + lane%4 + 4j][tapIdx] )
// ---------------------------------------------------------------------------
__global__ void pack_all(const float* __restrict__ w2, const float* __restrict__ w3,
                         const float* __restrict__ w4, const float* __restrict__ w5,
                         const float* __restrict__ w6, float* __restrict__ pk)
{
    int idx = blockIdx.x * blockDim.x + threadIdx.x;
    if (idx >= 138240) return;
    const float* w; int CIN, NCH, TAPS_, local;
    if (idx < 9216)       { w = w2; CIN = 32;  NCH = 4;  TAPS_ = 9; local = idx; }
    else if (idx < 27648) { w = w3; CIN = 32;  NCH = 4;  TAPS_ = 9; local = idx - 9216; }
    else if (idx < 64512) { w = w4; CIN = 64;  NCH = 8;  TAPS_ = 9; local = idx - 27648; }
    else if (idx < 89088) { w = w5; CIN = 64;  NCH = 8;  TAPS_ = 3; local = idx - 64512; }
    else                  { w = w6; CIN = 128; NCH = 16; TAPS_ = 3; local = idx - 89088; }
    int j    = local & 1;
    int r1   = local >> 1;
    int lane = r1 & 31;
    int r2   = r1 >> 5;
    int gg   = r2 & 3;
    int r3   = r2 >> 2;
    int tap  = r3 % TAPS_;
    int r4   = r3 / TAPS_;
    int t    = r4 % NCH;
    int ocg  = r4 / NCH;
    int oc   = ocg * 32 + gg * 8 + (lane >> 2);
    int cin  = t * 8 + (lane & 3) + 4 * j;
    int tapIdx = (TAPS_ == 3) ? (tap + 3) : tap;
    pk[idx] = tf32r(w[(oc * CIN + cin) * 9 + tapIdx]);
}

// ---------------------------------------------------------------------------
// conv1: 5x5, Cin=1, Cout=32, packed f32x2 FMA.
// ---------------------------------------------------------------------------
__global__ __launch_bounds__(256, 2)
void conv5x5_c1(const float* __restrict__ in, const float* __restrict__ wgt,
                float* __restrict__ out)
{
    const int H = 1024, W = 256, SL = 512, TH = 4, TW = 64;
    const int n  = blockIdx.z;
    const int h0 = blockIdx.y * TH;
    const int w0 = blockIdx.x * TW;
    const int tid = threadIdx.x;
    const int ocb = (tid & 3) * 8;
    const int op0 = (tid & 3) * 4;
    const int lw  = ((tid >> 2) & 15) * 4;
    const int hh  = tid >> 6;

    __shared__ float si[TH + 4][TW + 4];
    __shared__ float2 swp[16][25];

    for (int i = tid; i < 32 * 25; i += 256) {
        int o = i / 25, t = i % 25;
        float v = wgt[i];
        if (o & 1) swp[o >> 1][t].y = v; else swp[o >> 1][t].x = v;
    }

    const int ss = (h0 / SL) * SL, se = ss + SL;
    for (int i = tid; i < (TH + 4) * (TW + 4); i += 256) {
        int r = i / (TW + 4), c = i % (TW + 4);
        int g = h0 - 2 + r, gc = w0 - 2 + c;
        float v = 0.0f;
        if (g >= ss && g < se && gc >= 0 && gc < W)
            v = in[(n * H + g) * W + gc];
        si[r][c] = v;
    }
    __syncthreads();

    u64 dup[5][8];
#pragma unroll
    for (int r = 0; r < 5; r++)
#pragma unroll
        for (int c = 0; c < 8; c++)
            dup[r][c] = dup_f(si[hh + r][lw + c]);

    u64 acc[4][4];
#pragma unroll
    for (int p = 0; p < 4; p++)
#pragma unroll
        for (int x = 0; x < 4; x++) acc[p][x] = 0ULL;

#pragma unroll
    for (int p = 0; p < 4; p++) {
        const u64* wp = reinterpret_cast<const u64*>(&swp[op0 + p][0]);
#pragma unroll
        for (int r = 0; r < 5; r++)
#pragma unroll
            for (int kc = 0; kc < 5; kc++) {
                u64 wv = wp[r * 5 + kc];
#pragma unroll
                for (int x = 0; x < 4; x++)
                    ffma2(acc[p][x], dup[r][kc + x], wv);
            }
    }

#pragma unroll
    for (int p = 0; p < 4; p++) {
        float lo[4], hi[4];
#pragma unroll
        for (int x = 0; x < 4; x++) {
            float2 f = unpk(acc[p][x]);
            lo[x] = tf32r(dlrelu(f.x));
            hi[x] = tf32r(dlrelu(f.y));
        }
        int oc0 = ocb + 2 * p;
        float* o0 = &out[(((n * 32) + oc0) * H + h0 + hh) * W + w0 + lw];
        float* o1 = o0 + (size_t)H * W;
        *reinterpret_cast<float4*>(o0) = make_float4(lo[0], lo[1], lo[2], lo[3]);
        *reinterpret_cast<float4*>(o1) = make_float4(hi[0], hi[1], hi[2], hi[3]);
    }
}

// ---------------------------------------------------------------------------
// TF32 implicit-GEMM 3x3 focal conv.
// Block tile: 8h x 32w x 32oc. 8 warps; warp = one h row, M=32 x N=32
// (2 M-subtiles x 4 N-subtiles = 8 mmas per tap).
// ONEROW: sliceH==1 -> 1x3 conv with middle weight row, no h-halo.
// POOL: fuse 2x2 maxpool in epilogue; stash aliases the dead smem arena.
// ---------------------------------------------------------------------------
template <int CIN, int ONEROW, int POOL>
__global__ __launch_bounds__(256, 3)
void conv3x3_mma(const float* __restrict__ in, const float* __restrict__ pk,
                 float* __restrict__ out, int H, int W, int sliceH, int OCG,
                 int doRound)
{
    constexpr int CC    = 8;
    constexpr int TH    = 8;
    constexpr int ROWS  = ONEROW ? TH : (TH + 2);
    constexpr int TAPS  = ONEROW ? 3 : 9;
    constexpr int PLANE = ONEROW ? 328 : 424;   // >=ROWS*40, ==8 mod 32, /4
    constexpr int SI_W  = CC * PLANE;
    constexpr int CHUNK_W = TAPS * 256;
    constexpr int NCH   = CIN / CC;
    constexpr int NROWOPS = CC * ROWS * 10;     // 9 cp16 + 1 cp4 per row
    constexpr int NI    = (NROWOPS + 255) / 256;
    constexpr int NWOPS = TAPS * 64;
    constexpr int NW    = (NWOPS + 255) / 256;
    constexpr int ARENA = 2 * SI_W + 2 * CHUNK_W;

    // POOL stash: 8 * 32 * 33 = 8448 words, aliases full (dead) arena.
    static_assert(!POOL || ARENA >= TH * 32 * 33, "pool stash fits");

    __shared__ __align__(16) float arena[ARENA];
    float* si[2] = { arena, arena + SI_W };
    float* sb[2] = { arena + 2 * SI_W, arena + 2 * SI_W + CHUNK_W };
    float* sO = arena;

    const int z    = blockIdx.z;
    const int ocg  = z % OCG;
    const int n    = z / OCG;
    const int Cout = OCG * 32;
    const int h0   = blockIdx.y * TH;
    const int w0   = blockIdx.x * 32;
    const int tid  = threadIdx.x;
    const int lane = tid & 31;
    const int wid  = tid >> 5;      // h row within tile
    const int g2 = lane >> 2;
    const int g4 = lane & 3;

    const int ss = ONEROW ? 0 : (h0 / sliceH) * sliceH;
    const int se = ss + sliceH;

    const float* base = in + (size_t)n * CIN * H * W;
    const float* pk0  = pk + (size_t)(ocg * NCH) * CHUNK_W;

    // ---- hoisted input staging descriptors (cold; may spill) ----
    int di_dst[NI], di_off[NI];
#pragma unroll
    for (int k = 0; k < NI; k++) {
        int i = tid + k * 256;
        int dst = -1, off = -1;
        if (i < NROWOPS) {
            int rowid = i / 10, sub = i - rowid * 10;
            int c = rowid / ROWS, r = rowid - c * ROWS;
            int g = ONEROW ? (h0 + r) : (h0 - 1 + r);
            bool rowok = ONEROW ? true : (g >= ss && g < se);
            int word = c * PLANE + r * 40 + sub * 4;
            if (sub < 9) {
                int gc = w0 - 4 + sub * 4;
                dst = (word * 4) | 1;
                off = (rowok && gc >= 0) ? ((c * H + g) * W + gc) : -1;
            } else {
                int gc = w0 + 32;
                dst = word * 4;
                off = (rowok && gc < W) ? ((c * H + g) * W + gc) : -1;
            }
        }
        di_dst[k] = dst; di_off[k] = off;
    }

    unsigned si_s[2], sb_s[2];
    si_s[0] = (unsigned)__cvta_generic_to_shared(si[0]);
    si_s[1] = (unsigned)__cvta_generic_to_shared(si[1]);
    sb_s[0] = (unsigned)__cvta_generic_to_shared(sb[0]);
    sb_s[1] = (unsigned)__cvta_generic_to_shared(sb[1]);

    auto stage = [&](int t, int buf) {
        const float* cb = base + (size_t)t * CC * H * W;
        unsigned sd = si_s[buf];
#pragma unroll
        for (int k = 0; k < NI; k++) {
            int d = di_dst[k];
            if (d >= 0) {
                int off = di_off[k];
                if (d & 1)
                    cp16(sd + (unsigned)(d ^ 1),
                         off >= 0 ? (const void*)(cb + off) : (const void*)cb,
                         off >= 0 ? 16 : 0);
                else
                    cp4(sd + (unsigned)d,
                        off >= 0 ? (const void*)(cb + off) : (const void*)cb,
                        off >= 0 ? 4 : 0);
            }
        }
        const float* wb = pk0 + (size_t)t * CHUNK_W;
        unsigned wd = sb_s[buf];
#pragma unroll
        for (int k = 0; k < NW; k++) {
            int i = tid + k * 256;
            if (NWOPS % 256 == 0 || i < NWOPS)
                cp16(wd + (unsigned)i * 16, wb + i * 4, 16);
        }
        cp_commit();
    };

    float acc[2][4][4];
#pragma unroll
    for (int m = 0; m < 2; m++)
#pragma unroll
        for (int nn = 0; nn < 4; nn++)
#pragma unroll
            for (int x = 0; x < 4; x++) acc[m][nn][x] = 0.0f;

    const int abase = g4 * PLANE + wid * 40 + g2 + 3;
    const int a2off = 4 * PLANE;

    stage(0, 0);

    for (int t = 0; t < NCH; t++) {
        int buf = t & 1;
        if (t + 1 < NCH) {
            stage(t + 1, buf ^ 1);
            asm volatile("cp.async.wait_group 1;\n" ::);
        } else {
            asm volatile("cp.async.wait_group 0;\n" ::);
        }
        __syncthreads();

        const float* sif = si[buf];
        const float* sbf = sb[buf];
#pragma unroll
        for (int r = 0; r < (ONEROW ? 1 : 3); r++) {
#pragma unroll
            for (int q = 0; q < 3; q++) {
                const int tap = r * 3 + q;
                uint b[4][2];
#pragma unroll
                for (int nn = 0; nn < 4; nn++) {
                    float2 v = *reinterpret_cast<const float2*>(
                        sbf + ((tap * 4 + nn) * 32 + lane) * 2);
                    b[nn][0] = __float_as_uint(v.x);
                    b[nn][1] = __float_as_uint(v.y);
                }
#pragma unroll
                for (int m = 0; m < 2; m++) {
                    int ai = abase + r * 40 + q + m * 16;
                    uint a0 = __float_as_uint(sif[ai]);
                    uint a1 = __float_as_uint(sif[ai + 8]);
                    uint a2 = __float_as_uint(sif[ai + a2off]);
                    uint a3 = __float_as_uint(sif[ai + a2off + 8]);
#pragma unroll
                    for (int nn = 0; nn < 4; nn++)
                        mma_tf32(acc[m][nn], a0, a1, a2, a3,
                                 b[nn][0], b[nn][1]);
                }
            }
        }
        __syncthreads();
    }

    // ---- epilogue ----
    if (POOL) {
        // Arena is dead now (trailing __syncthreads). Stash activated +
        // rounded values [h:8][w:32][oc:32 pad33], then pooled write.
#pragma unroll
        for (int m = 0; m < 2; m++)
#pragma unroll
            for (int nn = 0; nn < 4; nn++) {
                int ocl = nn * 8 + 2 * g4;
#pragma unroll
                for (int x = 0; x < 4; x++) {
                    int wl = m * 16 + g2 + ((x >> 1) ? 8 : 0);
                    sO[wid * (32 * 33) + wl * 33 + ocl + (x & 1)] =
                        tf32r(dlrelu(acc[m][nn][x]));
                }
            }
        __syncthreads();
        const int H2 = H >> 1, W2 = W >> 1;
        const int pw = tid & 15, ph = (tid >> 4) & 3, ob = tid >> 6;
#pragma unroll
        for (int k = 0; k < 8; k++) {
            int ocl = ob * 8 + k;
            const float* s0 = sO + (2 * ph) * (32 * 33) + (2 * pw) * 33 + ocl;
            float v = fmaxf(fmaxf(s0[0], s0[33]),
                            fmaxf(s0[32 * 33], s0[32 * 33 + 33]));
            out[((size_t)(n * Cout + ocg * 32 + ocl) * H2 + (h0 >> 1) + ph) * W2
                + (w0 >> 1) + pw] = v;
        }
    } else {
        const int h = h0 + wid;
#pragma unroll
        for (int m = 0; m < 2; m++) {
#pragma unroll
            for (int nn = 0; nn < 4; nn++) {
                int oc = ocg * 32 + nn * 8 + 2 * g4;
                int wv = w0 + m * 16 + g2;
                float* p0 = out + ((size_t)(n * Cout + oc) * H + h) * W + wv;
                float* p1 = p0 + (size_t)H * W;
                float v0 = dlrelu(acc[m][nn][0]);
                float v1 = dlrelu(acc[m][nn][1]);
                float v2 = dlrelu(acc[m][nn][2]);
                float v3 = dlrelu(acc[m][nn][3]);
                if (doRound) { v0 = tf32r(v0); v1 = tf32r(v1);
                               v2 = tf32r(v2); v3 = tf32r(v3); }
                p0[0] = v0; p1[0] = v1; p0[8] = v2; p1[8] = v3;
            }
        }
    }
}

// ---------------------------------------------------------------------------
extern "C" void kernel_launch(void* const* d_in, const int* in_sizes, int n_in,
                              void* d_out, int out_size)
{
    const float* x  = (const float*)d_in[0];
    const float* w1 = (const float*)d_in[1];
    const float* w2 = (const float*)d_in[2];
    const float* w3 = (const float*)d_in[3];
    const float* w4 = (const float*)d_in[4];
    const float* w5 = (const float*)d_in[5];
    const float* w6 = (const float*)d_in[6];
    float* out = (float*)d_out;

    float *A, *B, *Wp;
    cudaGetSymbolAddress((void**)&A, g_bufA);
    cudaGetSymbolAddress((void**)&B, g_bufB);
    cudaGetSymbolAddress((void**)&Wp, g_bufW);

    const int o2 = 0, o3 = 9216, o4 = 27648, o5 = 64512, o6 = 89088;

    // Prep: fused round + pack of all conv weights.
    pack_all<<<540, 256>>>(w2, w3, w4, w5, w6, Wp);

    // conv1: x [2,1,1024,256] -> A [2,32,1024,256]
    conv5x5_c1<<<dim3(4, 256, 2), 256>>>(x, w1, A);

    // conv2 (+pool1 fused): A -> B [2,32,512,128]
    conv3x3_mma<32, 0, 1><<<dim3(8, 128, 2), 256>>>(A, Wp + o2, B,
                                                    1024, 256, 512, 1, 1);

    // conv3: B -> A [2,64,512,128] (sliceH=32)
    conv3x3_mma<32, 0, 0><<<dim3(4, 64, 4), 256>>>(B, Wp + o3, A,
                                                   512, 128, 32, 2, 1);

    // conv4 (+pool2 fused): A -> B [2,64,256,64]
    conv3x3_mma<64, 0, 1><<<dim3(4, 64, 4), 256>>>(A, Wp + o4, B,
                                                   512, 128, 32, 2, 1);

    // conv5: B -> A [2,128,256,64] (1x3 middle row)
    conv3x3_mma<64, 1, 0><<<dim3(2, 32, 8), 256>>>(B, Wp + o5, A,
                                                   256, 64, 1, 4, 1);

    // conv6: A -> out (final: no rounding)
    conv3x3_mma<128, 1, 0><<<dim3(2, 32, 8), 256>>>(A, Wp + o6, out,
                                                    256, 64, 1, 4, 0);
}

// round 10
// speedup vs baseline: 1.2265x; 1.2265x over previous
#include <cuda_runtime.h>

// ---------------------------------------------------------------------------
// FrameLevelPartFeatureExtractor — TF32 tensor-core (mma.sync m16n8k8) conv
// pipeline. conv1 packed-f32x2; conv2..conv6 implicit GEMM on HMMA with
// 8h x 32w x 32oc block tile (warp = 1 h-row, M=32 x N=32).
// R10: 3-stage cp.async pipeline with ONE __syncthreads per cin-chunk
// (dynamic smem, 68.4KB / 40.7KB per block). conv2/conv4 fuse the 2x2
// maxpool into their epilogue. Intermediates tf32-rounded; final fp32.
// ---------------------------------------------------------------------------

typedef unsigned int uint;
typedef unsigned long long u64;

__device__ __align__(16) float g_bufA[16777216];
__device__ __align__(16) float g_bufB[16777216];
__device__ __align__(16) float g_bufW[138240];   // packed tf32 weights, w2..w6

__device__ __forceinline__ float dlrelu(float v) {
    return v > 0.0f ? v : 0.01f * (0.01f * v);
}
__device__ __forceinline__ float tf32r(float v) {
    uint u; asm("cvt.rna.tf32.f32 %0, %1;" : "=r"(u) : "f"(v));
    return __uint_as_float(u);
}
__device__ __forceinline__ void cp16(unsigned dst, const void* src, int sz) {
    asm volatile("cp.async.cg.shared.global [%0], [%1], 16, %2;\n"
                 :: "r"(dst), "l"(src), "r"(sz));
}
__device__ __forceinline__ void cp4(unsigned dst, const void* src, int sz) {
    asm volatile("cp.async.ca.shared.global [%0], [%1], 4, %2;\n"
                 :: "r"(dst), "l"(src), "r"(sz));
}
__device__ __forceinline__ void cp_commit() {
    asm volatile("cp.async.commit_group;\n" ::);
}
__device__ __forceinline__ void mma_tf32(float* c, uint a0, uint a1, uint a2,
                                         uint a3, uint b0, uint b1) {
    asm volatile(
        "mma.sync.aligned.m16n8k8.row.col.f32.tf32.tf32.f32 "
        "{%0,%1,%2,%3}, {%4,%5,%6,%7}, {%8,%9}, {%0,%1,%2,%3};"
        : "+f"(c[0]), "+f"(c[1]), "+f"(c[2]), "+f"(c[3])
        : "r"(a0), "r"(a1), "r"(a2), "r"(a3), "r"(b0), "r"(b1));
}
__device__ __forceinline__ u64 dup_f(float v) {
    u64 r; asm("mov.b64 %0, {%1, %1};" : "=l"(r) : "f"(v)); return r;
}
__device__ __forceinline__ void ffma2(u64& d, u64 a, u64 b) {
    asm("fma.rn.f32x2 %0, %1, %2, %0;" : "+l"(d) : "l"(a), "l"(b));
}
__device__ __forceinline__ float2 unpk(u64 a) {
    float2 f; asm("mov.b64 {%0, %1}, %2;" : "=f"(f.x), "=f"(f.y) : "l"(a));
    return f;
}

// ---------------------------------------------------------------------------
// Fused weight pack for layers 2..6 (layout unchanged):
// pk[((ocg*NCH + t)*TAPS + tap)*4 + gg][lane][j] =
//   tf32( W[ocg*32 + gg*8 + lane/4][t*8 + lane%4 + 4j][tapIdx] )
// ---------------------------------------------------------------------------
__global__ void pack_all(const float* __restrict__ w2, const float* __restrict__ w3,
                         const float* __restrict__ w4, const float* __restrict__ w5,
                         const float* __restrict__ w6, float* __restrict__ pk)
{
    int idx = blockIdx.x * blockDim.x + threadIdx.x;
    if (idx >= 138240) return;
    const float* w; int CIN, NCH, TAPS_, local;
    if (idx < 9216)       { w = w2; CIN = 32;  NCH = 4;  TAPS_ = 9; local = idx; }
    else if (idx < 27648) { w = w3; CIN = 32;  NCH = 4;  TAPS_ = 9; local = idx - 9216; }
    else if (idx < 64512) { w = w4; CIN = 64;  NCH = 8;  TAPS_ = 9; local = idx - 27648; }
    else if (idx < 89088) { w = w5; CIN = 64;  NCH = 8;  TAPS_ = 3; local = idx - 64512; }
    else                  { w = w6; CIN = 128; NCH = 16; TAPS_ = 3; local = idx - 89088; }
    int j    = local & 1;
    int r1   = local >> 1;
    int lane = r1 & 31;
    int r2   = r1 >> 5;
    int gg   = r2 & 3;
    int r3   = r2 >> 2;
    int tap  = r3 % TAPS_;
    int r4   = r3 / TAPS_;
    int t    = r4 % NCH;
    int ocg  = r4 / NCH;
    int oc   = ocg * 32 + gg * 8 + (lane >> 2);
    int cin  = t * 8 + (lane & 3) + 4 * j;
    int tapIdx = (TAPS_ == 3) ? (tap + 3) : tap;
    pk[idx] = tf32r(w[(oc * CIN + cin) * 9 + tapIdx]);
}

// ---------------------------------------------------------------------------
// conv1: 5x5, Cin=1, Cout=32, packed f32x2 FMA.
// ---------------------------------------------------------------------------
__global__ __launch_bounds__(256, 2)
void conv5x5_c1(const float* __restrict__ in, const float* __restrict__ wgt,
                float* __restrict__ out)
{
    const int H = 1024, W = 256, SL = 512, TH = 4, TW = 64;
    const int n  = blockIdx.z;
    const int h0 = blockIdx.y * TH;
    const int w0 = blockIdx.x * TW;
    const int tid = threadIdx.x;
    const int ocb = (tid & 3) * 8;
    const int op0 = (tid & 3) * 4;
    const int lw  = ((tid >> 2) & 15) * 4;
    const int hh  = tid >> 6;

    __shared__ float si[TH + 4][TW + 4];
    __shared__ float2 swp[16][25];

    for (int i = tid; i < 32 * 25; i += 256) {
        int o = i / 25, t = i % 25;
        float v = wgt[i];
        if (o & 1) swp[o >> 1][t].y = v; else swp[o >> 1][t].x = v;
    }

    const int ss = (h0 / SL) * SL, se = ss + SL;
    for (int i = tid; i < (TH + 4) * (TW + 4); i += 256) {
        int r = i / (TW + 4), c = i % (TW + 4);
        int g = h0 - 2 + r, gc = w0 - 2 + c;
        float v = 0.0f;
        if (g >= ss && g < se && gc >= 0 && gc < W)
            v = in[(n * H + g) * W + gc];
        si[r][c] = v;
    }
    __syncthreads();

    u64 dup[5][8];
#pragma unroll
    for (int r = 0; r < 5; r++)
#pragma unroll
        for (int c = 0; c < 8; c++)
            dup[r][c] = dup_f(si[hh + r][lw + c]);

    u64 acc[4][4];
#pragma unroll
    for (int p = 0; p < 4; p++)
#pragma unroll
        for (int x = 0; x < 4; x++) acc[p][x] = 0ULL;

#pragma unroll
    for (int p = 0; p < 4; p++) {
        const u64* wp = reinterpret_cast<const u64*>(&swp[op0 + p][0]);
#pragma unroll
        for (int r = 0; r < 5; r++)
#pragma unroll
            for (int kc = 0; kc < 5; kc++) {
                u64 wv = wp[r * 5 + kc];
#pragma unroll
                for (int x = 0; x < 4; x++)
                    ffma2(acc[p][x], dup[r][kc + x], wv);
            }
    }

#pragma unroll
    for (int p = 0; p < 4; p++) {
        float lo[4], hi[4];
#pragma unroll
        for (int x = 0; x < 4; x++) {
            float2 f = unpk(acc[p][x]);
            lo[x] = tf32r(dlrelu(f.x));
            hi[x] = tf32r(dlrelu(f.y));
        }
        int oc0 = ocb + 2 * p;
        float* o0 = &out[(((n * 32) + oc0) * H + h0 + hh) * W + w0 + lw];
        float* o1 = o0 + (size_t)H * W;
        *reinterpret_cast<float4*>(o0) = make_float4(lo[0], lo[1], lo[2], lo[3]);
        *reinterpret_cast<float4*>(o1) = make_float4(hi[0], hi[1], hi[2], hi[3]);
    }
}

// ---------------------------------------------------------------------------
// TF32 implicit-GEMM 3x3 focal conv, 3-stage cp.async pipeline (1 sync/chunk).
// Block tile: 8h x 32w x 32oc. 8 warps; warp = one h row, M=32 x N=32.
// ONEROW: sliceH==1 -> 1x3 conv with middle weight row, no h-halo.
// POOL: fuse 2x2 maxpool in epilogue; stash aliases the dead smem arena.
// Dynamic smem: 3*(SI_W + CHUNK_W) floats.
// ---------------------------------------------------------------------------
template <int CIN, int ONEROW, int POOL>
__global__ __launch_bounds__(256, 3)
void conv3x3_mma(const float* __restrict__ in, const float* __restrict__ pk,
                 float* __restrict__ out, int H, int W, int sliceH, int OCG,
                 int doRound)
{
    constexpr int CC    = 8;
    constexpr int TH    = 8;
    constexpr int ROWS  = ONEROW ? TH : (TH + 2);
    constexpr int TAPS  = ONEROW ? 3 : 9;
    constexpr int PLANE = ONEROW ? 328 : 424;   // >=ROWS*40, ==8 mod 32, /4
    constexpr int SI_W  = CC * PLANE;
    constexpr int CHUNK_W = TAPS * 256;
    constexpr int NCH   = CIN / CC;
    constexpr int NROWOPS = CC * ROWS * 10;     // 9 cp16 + 1 cp4 per row
    constexpr int NI    = (NROWOPS + 255) / 256;
    constexpr int NWOPS = TAPS * 64;
    constexpr int NW    = (NWOPS + 255) / 256;
    constexpr int ARENA = 3 * (SI_W + CHUNK_W);

    // POOL stash: 8 * 32 * 33 = 8448 words, aliases the (dead) arena.
    static_assert(!POOL || ARENA >= TH * 32 * 33, "pool stash fits");
    static_assert(NCH >= 3, "pipeline needs >= 3 chunks");

    extern __shared__ __align__(16) float arena[];
    float* si_p = arena;
    float* sb_p = arena + 3 * SI_W;
    float* sO   = arena;

    const int z    = blockIdx.z;
    const int ocg  = z % OCG;
    const int n    = z / OCG;
    const int Cout = OCG * 32;
    const int h0   = blockIdx.y * TH;
    const int w0   = blockIdx.x * 32;
    const int tid  = threadIdx.x;
    const int lane = tid & 31;
    const int wid  = tid >> 5;      // h row within tile
    const int g2 = lane >> 2;
    const int g4 = lane & 3;

    const int ss = ONEROW ? 0 : (h0 / sliceH) * sliceH;
    const int se = ss + sliceH;

    const float* base = in + (size_t)n * CIN * H * W;
    const float* pk0  = pk + (size_t)(ocg * NCH) * CHUNK_W;

    // ---- hoisted input staging descriptors ----
    int di_dst[NI], di_off[NI];
#pragma unroll
    for (int k = 0; k < NI; k++) {
        int i = tid + k * 256;
        int dst = -1, off = -1;
        if (i < NROWOPS) {
            int rowid = i / 10, sub = i - rowid * 10;
            int c = rowid / ROWS, r = rowid - c * ROWS;
            int g = ONEROW ? (h0 + r) : (h0 - 1 + r);
            bool rowok = ONEROW ? true : (g >= ss && g < se);
            int word = c * PLANE + r * 40 + sub * 4;
            if (sub < 9) {
                int gc = w0 - 4 + sub * 4;
                dst = (word * 4) | 1;
                off = (rowok && gc >= 0) ? ((c * H + g) * W + gc) : -1;
            } else {
                int gc = w0 + 32;
                dst = word * 4;
                off = (rowok && gc < W) ? ((c * H + g) * W + gc) : -1;
            }
        }
        di_dst[k] = dst; di_off[k] = off;
    }

    unsigned si_s = (unsigned)__cvta_generic_to_shared(si_p);
    unsigned sb_s = (unsigned)__cvta_generic_to_shared(sb_p);

    auto stage = [&](int t, int buf) {
        const float* cb = base + (size_t)t * CC * H * W;
        unsigned sd = si_s + (unsigned)buf * (SI_W * 4);
#pragma unroll
        for (int k = 0; k < NI; k++) {
            int d = di_dst[k];
            if (d >= 0) {
                int off = di_off[k];
                if (d & 1)
                    cp16(sd + (unsigned)(d ^ 1),
                         off >= 0 ? (const void*)(cb + off) : (const void*)cb,
                         off >= 0 ? 16 : 0);
                else
                    cp4(sd + (unsigned)d,
                        off >= 0 ? (const void*)(cb + off) : (const void*)cb,
                        off >= 0 ? 4 : 0);
            }
        }
        const float* wb = pk0 + (size_t)t * CHUNK_W;
        unsigned wd = sb_s + (unsigned)buf * (CHUNK_W * 4);
#pragma unroll
        for (int k = 0; k < NW; k++) {
            int i = tid + k * 256;
            if (NWOPS % 256 == 0 || i < NWOPS)
                cp16(wd + (unsigned)i * 16, wb + i * 4, 16);
        }
        cp_commit();
    };

    float acc[2][4][4];
#pragma unroll
    for (int m = 0; m < 2; m++)
#pragma unroll
        for (int nn = 0; nn < 4; nn++)
#pragma unroll
            for (int x = 0; x < 4; x++) acc[m][nn][x] = 0.0f;

    const int abase = g4 * PLANE + wid * 40 + g2 + 3;
    const int a2off = 4 * PLANE;

    stage(0, 0);
    stage(1, 1);

    for (int t = 0; t < NCH; t++) {
        if (t + 1 < NCH) asm volatile("cp.async.wait_group 1;\n" ::);
        else             asm volatile("cp.async.wait_group 0;\n" ::);
        __syncthreads();
        if (t + 2 < NCH) stage(t + 2, (t + 2) % 3);

        const float* sif = si_p + (t % 3) * SI_W;
        const float* sbf = sb_p + (t % 3) * CHUNK_W;
#pragma unroll
        for (int r = 0; r < (ONEROW ? 1 : 3); r++) {
#pragma unroll
            for (int q = 0; q < 3; q++) {
                const int tap = r * 3 + q;
                uint b[4][2];
#pragma unroll
                for (int nn = 0; nn < 4; nn++) {
                    float2 v = *reinterpret_cast<const float2*>(
                        sbf + ((tap * 4 + nn) * 32 + lane) * 2);
                    b[nn][0] = __float_as_uint(v.x);
                    b[nn][1] = __float_as_uint(v.y);
                }
#pragma unroll
                for (int m = 0; m < 2; m++) {
                    int ai = abase + r * 40 + q + m * 16;
                    uint a0 = __float_as_uint(sif[ai]);
                    uint a1 = __float_as_uint(sif[ai + 8]);
                    uint a2 = __float_as_uint(sif[ai + a2off]);
                    uint a3 = __float_as_uint(sif[ai + a2off + 8]);
#pragma unroll
                    for (int nn = 0; nn < 4; nn++)
                        mma_tf32(acc[m][nn], a0, a1, a2, a3,
                                 b[nn][0], b[nn][1]);
                }
            }
        }
    }

    // ---- epilogue ----
    if (POOL) {
        __syncthreads();   // all warps done with arena before stash aliasing
#pragma unroll
        for (int m = 0; m < 2; m++)
#pragma unroll
            for (int nn = 0; nn < 4; nn++) {
                int ocl = nn * 8 + 2 * g4;
#pragma unroll
                for (int x = 0; x < 4; x++) {
                    int wl = m * 16 + g2 + ((x >> 1) ? 8 : 0);
                    sO[wid * (32 * 33) + wl * 33 + ocl + (x & 1)] =
                        tf32r(dlrelu(acc[m][nn][x]));
                }
            }
        __syncthreads();
        const int H2 = H >> 1, W2 = W >> 1;
        const int pw = tid & 15, ph = (tid >> 4) & 3, ob = tid >> 6;
#pragma unroll
        for (int k = 0; k < 8; k++) {
            int ocl = ob * 8 + k;
            const float* s0 = sO + (2 * ph) * (32 * 33) + (2 * pw) * 33 + ocl;
            float v = fmaxf(fmaxf(s0[0], s0[33]),
                            fmaxf(s0[32 * 33], s0[32 * 33 + 33]));
            out[((size_t)(n * Cout + ocg * 32 + ocl) * H2 + (h0 >> 1) + ph) * W2
                + (w0 >> 1) + pw] = v;
        }
    } else {
        const int h = h0 + wid;
#pragma unroll
        for (int m = 0; m < 2; m++) {
#pragma unroll
            for (int nn = 0; nn < 4; nn++) {
                int oc = ocg * 32 + nn * 8 + 2 * g4;
                int wv = w0 + m * 16 + g2;
                float* p0 = out + ((size_t)(n * Cout + oc) * H + h) * W + wv;
                float* p1 = p0 + (size_t)H * W;
                float v0 = dlrelu(acc[m][nn][0]);
                float v1 = dlrelu(acc[m][nn][1]);
                float v2 = dlrelu(acc[m][nn][2]);
                float v3 = dlrelu(acc[m][nn][3]);
                if (doRound) { v0 = tf32r(v0); v1 = tf32r(v1);
                               v2 = tf32r(v2); v3 = tf32r(v3); }
                p0[0] = v0; p1[0] = v1; p0[8] = v2; p1[8] = v3;
            }
        }
    }
}

// ---------------------------------------------------------------------------
extern "C" void kernel_launch(void* const* d_in, const int* in_sizes, int n_in,
                              void* d_out, int out_size)
{
    const float* x  = (const float*)d_in[0];
    const float* w1 = (const float*)d_in[1];
    const float* w2 = (const float*)d_in[2];
    const float* w3 = (const float*)d_in[3];
    const float* w4 = (const float*)d_in[4];
    const float* w5 = (const float*)d_in[5];
    const float* w6 = (const float*)d_in[6];
    float* out = (float*)d_out;

    float *A, *B, *Wp;
    cudaGetSymbolAddress((void**)&A, g_bufA);
    cudaGetSymbolAddress((void**)&B, g_bufB);
    cudaGetSymbolAddress((void**)&Wp, g_bufW);

    const int o2 = 0, o3 = 9216, o4 = 27648, o5 = 64512, o6 = 89088;

    // Dynamic smem sizes (floats -> bytes)
    const int SM_FULL = 3 * (8 * 424 + 9 * 256) * 4;   // 68352B (non-ONEROW)
    const int SM_ONE  = 3 * (8 * 328 + 3 * 256) * 4;   // 40704B (ONEROW)

    cudaFuncSetAttribute(conv3x3_mma<32, 0, 1>,
                         cudaFuncAttributeMaxDynamicSharedMemorySize, SM_FULL);
    cudaFuncSetAttribute(conv3x3_mma<32, 0, 0>,
                         cudaFuncAttributeMaxDynamicSharedMemorySize, SM_FULL);
    cudaFuncSetAttribute(conv3x3_mma<64, 0, 1>,
                         cudaFuncAttributeMaxDynamicSharedMemorySize, SM_FULL);
    cudaFuncSetAttribute(conv3x3_mma<64, 1, 0>,
                         cudaFuncAttributeMaxDynamicSharedMemorySize, SM_ONE);
    cudaFuncSetAttribute(conv3x3_mma<128, 1, 0>,
                         cudaFuncAttributeMaxDynamicSharedMemorySize, SM_ONE);

    // Prep: fused round + pack of all conv weights.
    pack_all<<<540, 256>>>(w2, w3, w4, w5, w6, Wp);

    // conv1: x [2,1,1024,256] -> A [2,32,1024,256]
    conv5x5_c1<<<dim3(4, 256, 2), 256>>>(x, w1, A);

    // conv2 (+pool1 fused): A -> B [2,32,512,128]
    conv3x3_mma<32, 0, 1><<<dim3(8, 128, 2), 256, SM_FULL>>>(
        A, Wp + o2, B, 1024, 256, 512, 1, 1);

    // conv3: B -> A [2,64,512,128] (sliceH=32)
    conv3x3_mma<32, 0, 0><<<dim3(4, 64, 4), 256, SM_FULL>>>(
        B, Wp + o3, A, 512, 128, 32, 2, 1);

    // conv4 (+pool2 fused): A -> B [2,64,256,64]
    conv3x3_mma<64, 0, 1><<<dim3(4, 64, 4), 256, SM_FULL>>>(
        A, Wp + o4, B, 512, 128, 32, 2, 1);

    // conv5: B -> A [2,128,256,64] (1x3 middle row)
    conv3x3_mma<64, 1, 0><<<dim3(2, 32, 8), 256, SM_ONE>>>(
        B, Wp + o5, A, 256, 64, 1, 4, 1);

    // conv6: A -> out (final: no rounding)
    conv3x3_mma<128, 1, 0><<<dim3(2, 32, 8), 256, SM_ONE>>>(
        A, Wp + o6, out, 256, 64, 1, 4, 0);
}

// round 11
// speedup vs baseline: 2.1124x; 1.7224x over previous
#include <cuda_runtime.h>
#include <cuda_fp16.h>

// ---------------------------------------------------------------------------
// FrameLevelPartFeatureExtractor — FP16 tensor-core (mma.sync m16n8k16) conv
// pipeline. Intermediates stored fp16 in cpair-interleaved layout
// [N][C/2][H][W][2] (one 32-bit word = half2 of adjacent channels).
// conv1 packed-f32x2 fp32 compute -> fp16 out. conv2..conv6 implicit GEMM,
// 8h x 32w x 32oc block tile, 3-stage cp.async pipeline (1 sync/chunk),
// K-chunk = 16 cin. conv2/conv4 fuse 2x2 maxpool (max.f16x2). Final conv6
// writes plain fp32 NCHW.
// ---------------------------------------------------------------------------

typedef unsigned int uint;
typedef unsigned long long u64;

__device__ __align__(16) uint g_bufA[8388608];
__device__ __align__(16) uint g_bufB[8388608];
__device__ __align__(16) uint g_bufW[69120];   // packed fp16 weights, w2..w6

__device__ __forceinline__ float dlrelu(float v) {
    return v > 0.0f ? v : 0.01f * (0.01f * v);
}
// pack two floats -> half2 word (lo = first arg)
__device__ __forceinline__ uint pack_h2(float lo, float hi) {
    uint r; asm("cvt.rn.f16x2.f32 %0, %1, %2;" : "=r"(r) : "f"(hi), "f"(lo));
    return r;
}
__device__ __forceinline__ uint max_h2(uint a, uint b) {
    uint r; asm("max.f16x2 %0, %1, %2;" : "=r"(r) : "r"(a), "r"(b));
    return r;
}
__device__ __forceinline__ void cp16(unsigned dst, const void* src, int sz) {
    asm volatile("cp.async.cg.shared.global [%0], [%1], 16, %2;\n"
                 :: "r"(dst), "l"(src), "r"(sz));
}
__device__ __forceinline__ void cp4(unsigned dst, const void* src, int sz) {
    asm volatile("cp.async.ca.shared.global [%0], [%1], 4, %2;\n"
                 :: "r"(dst), "l"(src), "r"(sz));
}
__device__ __forceinline__ void cp_commit() {
    asm volatile("cp.async.commit_group;\n" ::);
}
__device__ __forceinline__ void mma_f16(float* c, uint a0, uint a1, uint a2,
                                        uint a3, uint b0, uint b1) {
    asm volatile(
        "mma.sync.aligned.m16n8k16.row.col.f32.f16.f16.f32 "
        "{%0,%1,%2,%3}, {%4,%5,%6,%7}, {%8,%9}, {%0,%1,%2,%3};"
        : "+f"(c[0]), "+f"(c[1]), "+f"(c[2]), "+f"(c[3])
        : "r"(a0), "r"(a1), "r"(a2), "r"(a3), "r"(b0), "r"(b1));
}
__device__ __forceinline__ u64 dup_f(float v) {
    u64 r; asm("mov.b64 %0, {%1, %1};" : "=l"(r) : "f"(v)); return r;
}
__device__ __forceinline__ void ffma2(u64& d, u64 a, u64 b) {
    asm("fma.rn.f32x2 %0, %1, %2, %0;" : "+l"(d) : "l"(a), "l"(b));
}
__device__ __forceinline__ float2 unpk(u64 a) {
    float2 f; asm("mov.b64 {%0, %1}, %2;" : "=f"(f.x), "=f"(f.y) : "l"(a));
    return f;
}

// ---------------------------------------------------------------------------
// Fused fp16 weight pack for layers 2..6.
// Word layout per layer: [ocg][t][tap][nn][lane][j], word = half2 of
//   W[oc = ocg*32 + nn*8 + lane/4][cin = t*16 + 2*((lane&3)+4j) (+1)][tapIdx]
// TAPS==3 -> middle kernel row (taps 3..5).
// Layer word sizes: 4608 / 9216 / 18432 / 12288 / 24576 (total 69120).
// ---------------------------------------------------------------------------
__global__ void pack_all(const float* __restrict__ w2, const float* __restrict__ w3,
                         const float* __restrict__ w4, const float* __restrict__ w5,
                         const float* __restrict__ w6, uint* __restrict__ pk)
{
    int idx = blockIdx.x * blockDim.x + threadIdx.x;
    if (idx >= 69120) return;
    const float* w; int CIN, NCH, TAPS_, local;
    if (idx < 4608)       { w = w2; CIN = 32;  NCH = 2; TAPS_ = 9; local = idx; }
    else if (idx < 13824) { w = w3; CIN = 32;  NCH = 2; TAPS_ = 9; local = idx - 4608; }
    else if (idx < 32256) { w = w4; CIN = 64;  NCH = 4; TAPS_ = 9; local = idx - 13824; }
    else if (idx < 44544) { w = w5; CIN = 64;  NCH = 4; TAPS_ = 3; local = idx - 32256; }
    else                  { w = w6; CIN = 128; NCH = 8; TAPS_ = 3; local = idx - 44544; }
    int j    = local & 1;
    int r1   = local >> 1;
    int lane = r1 & 31;
    int r2   = r1 >> 5;
    int nn   = r2 & 3;
    int r3   = r2 >> 2;
    int tap  = r3 % TAPS_;
    int r4   = r3 / TAPS_;
    int t    = r4 % NCH;
    int ocg  = r4 / NCH;
    int oc   = ocg * 32 + nn * 8 + (lane >> 2);
    int cin  = t * 16 + 2 * ((lane & 3) + 4 * j);
    int tapIdx = (TAPS_ == 3) ? (tap + 3) : tap;
    float v0 = w[(oc * CIN + cin) * 9 + tapIdx];
    float v1 = w[(oc * CIN + cin + 1) * 9 + tapIdx];
    pk[idx] = pack_h2(v0, v1);
}

// ---------------------------------------------------------------------------
// conv1: 5x5, Cin=1, Cout=32, packed f32x2 FMA; fp16 cpair-interleaved out.
// ---------------------------------------------------------------------------
__global__ __launch_bounds__(256, 2)
void conv5x5_c1(const float* __restrict__ in, const float* __restrict__ wgt,
                uint* __restrict__ out)
{
    const int H = 1024, W = 256, SL = 512, TH = 4, TW = 64;
    const int n  = blockIdx.z;
    const int h0 = blockIdx.y * TH;
    const int w0 = blockIdx.x * TW;
    const int tid = threadIdx.x;
    const int ocb = (tid & 3) * 8;
    const int op0 = (tid & 3) * 4;
    const int lw  = ((tid >> 2) & 15) * 4;
    const int hh  = tid >> 6;

    __shared__ float si[TH + 4][TW + 4];
    __shared__ float2 swp[16][25];

    for (int i = tid; i < 32 * 25; i += 256) {
        int o = i / 25, t = i % 25;
        float v = wgt[i];
        if (o & 1) swp[o >> 1][t].y = v; else swp[o >> 1][t].x = v;
    }

    const int ss = (h0 / SL) * SL, se = ss + SL;
    for (int i = tid; i < (TH + 4) * (TW + 4); i += 256) {
        int r = i / (TW + 4), c = i % (TW + 4);
        int g = h0 - 2 + r, gc = w0 - 2 + c;
        float v = 0.0f;
        if (g >= ss && g < se && gc >= 0 && gc < W)
            v = in[(n * H + g) * W + gc];
        si[r][c] = v;
    }
    __syncthreads();

    u64 dup[5][8];
#pragma unroll
    for (int r = 0; r < 5; r++)
#pragma unroll
        for (int c = 0; c < 8; c++)
            dup[r][c] = dup_f(si[hh + r][lw + c]);

    u64 acc[4][4];
#pragma unroll
    for (int p = 0; p < 4; p++)
#pragma unroll
        for (int x = 0; x < 4; x++) acc[p][x] = 0ULL;

#pragma unroll
    for (int p = 0; p < 4; p++) {
        const u64* wp = reinterpret_cast<const u64*>(&swp[op0 + p][0]);
#pragma unroll
        for (int r = 0; r < 5; r++)
#pragma unroll
            for (int kc = 0; kc < 5; kc++) {
                u64 wv = wp[r * 5 + kc];
#pragma unroll
                for (int x = 0; x < 4; x++)
                    ffma2(acc[p][x], dup[r][kc + x], wv);
            }
    }

#pragma unroll
    for (int p = 0; p < 4; p++) {
        uint4 st;
        uint* sv = &st.x;
#pragma unroll
        for (int x = 0; x < 4; x++) {
            float2 f = unpk(acc[p][x]);
            sv[x] = pack_h2(dlrelu(f.x), dlrelu(f.y));
        }
        int ocp = (tid & 3) * 4 + p;          // channel-pair index (0..15)
        uint* op = &out[(((size_t)n * 16 + ocp) * H + h0 + hh) * W + w0 + lw];
        *reinterpret_cast<uint4*>(op) = st;
    }
}

// ---------------------------------------------------------------------------
// FP16 implicit-GEMM 3x3 focal conv, 3-stage cp.async pipeline (1 sync/chunk).
// Block tile: 8h x 32w x 32oc, warp = one h row (M=32 x N=32). K-chunk = 16
// cin (8 cpair smem planes, words = half2 of adjacent cins).
// ONEROW: sliceH==1 -> 1x3 conv with middle weight row, no h-halo.
// POOL: fused 2x2 maxpool epilogue (stash aliases dead arena).
// FINAL: fp32 plain-NCHW output.
// ---------------------------------------------------------------------------
template <int CIN, int ONEROW, int POOL, int FINAL>
__global__ __launch_bounds__(256, 3)
void conv3x3_mma(const uint* __restrict__ in, const uint* __restrict__ pk,
                 void* __restrict__ outv, int H, int W, int sliceH, int OCG)
{
    constexpr int TH    = 8;
    constexpr int ROWS  = ONEROW ? TH : (TH + 2);
    constexpr int TAPS  = ONEROW ? 3 : 9;
    constexpr int PLANE = ONEROW ? 328 : 424;   // words; ==8 mod 32; mult of 4
    constexpr int SI_W  = 8 * PLANE;            // 8 cpair planes
    constexpr int CHUNK_W = TAPS * 256;
    constexpr int NCH   = CIN / 16;
    constexpr int NROWOPS = 8 * ROWS * 10;      // 9 cp16 + 1 cp4 per row
    constexpr int NI    = (NROWOPS + 255) / 256;
    constexpr int NWOPS = TAPS * 64;
    constexpr int NW    = (NWOPS + 255) / 256;
    constexpr int ARENA = 3 * (SI_W + CHUNK_W);

    static_assert(!POOL || ARENA >= TH * 32 * 18, "pool stash fits");
    static_assert(NCH >= 2, "pipeline needs >= 2 chunks");

    extern __shared__ __align__(16) uint arena[];
    uint* si_p = arena;
    uint* sb_p = arena + 3 * SI_W;
    uint* sO   = arena;

    const int z    = blockIdx.z;
    const int ocg  = z % OCG;
    const int n    = z / OCG;
    const int h0   = blockIdx.y * TH;
    const int w0   = blockIdx.x * 32;
    const int tid  = threadIdx.x;
    const int lane = tid & 31;
    const int wid  = tid >> 5;      // h row within tile
    const int g2 = lane >> 2;
    const int g4 = lane & 3;

    const int ss = ONEROW ? 0 : (h0 / sliceH) * sliceH;
    const int se = ss + sliceH;

    const int C2in = CIN / 2;
    const uint* base = in + (size_t)n * C2in * H * W;
    const uint* pk0  = pk + (size_t)(ocg * NCH) * CHUNK_W;

    // ---- hoisted input staging descriptors ----
    int di_dst[NI], di_off[NI];
#pragma unroll
    for (int k = 0; k < NI; k++) {
        int i = tid + k * 256;
        int dst = -1, off = -1;
        if (i < NROWOPS) {
            int rowid = i / 10, sub = i - rowid * 10;
            int c = rowid / ROWS, r = rowid - c * ROWS;   // c = cpair 0..7
            int g = ONEROW ? (h0 + r) : (h0 - 1 + r);
            bool rowok = ONEROW ? true : (g >= ss && g < se);
            int word = c * PLANE + r * 40 + sub * 4;
            if (sub < 9) {
                int gc = w0 - 4 + sub * 4;
                dst = (word * 4) | 1;
                off = (rowok && gc >= 0) ? ((c * H + g) * W + gc) : -1;
            } else {
                int gc = w0 + 32;
                dst = word * 4;
                off = (rowok && gc < W) ? ((c * H + g) * W + gc) : -1;
            }
        }
        di_dst[k] = dst; di_off[k] = off;
    }

    unsigned si_s = (unsigned)__cvta_generic_to_shared(si_p);
    unsigned sb_s = (unsigned)__cvta_generic_to_shared(sb_p);

    auto stage = [&](int t, int buf) {
        const uint* cb = base + (size_t)t * 8 * H * W;   // 8 cpairs per chunk
        unsigned sd = si_s + (unsigned)buf * (SI_W * 4);
#pragma unroll
        for (int k = 0; k < NI; k++) {
            int d = di_dst[k];
            if (d >= 0) {
                int off = di_off[k];
                if (d & 1)
                    cp16(sd + (unsigned)(d ^ 1),
                         off >= 0 ? (const void*)(cb + off) : (const void*)cb,
                         off >= 0 ? 16 : 0);
                else
                    cp4(sd + (unsigned)d,
                        off >= 0 ? (const void*)(cb + off) : (const void*)cb,
                        off >= 0 ? 4 : 0);
            }
        }
        const uint* wb = pk0 + (size_t)t * CHUNK_W;
        unsigned wd = sb_s + (unsigned)buf * (CHUNK_W * 4);
#pragma unroll
        for (int k = 0; k < NW; k++) {
            int i = tid + k * 256;
            if (NWOPS % 256 == 0 || i < NWOPS)
                cp16(wd + (unsigned)i * 16, wb + i * 4, 16);
        }
        cp_commit();
    };

    float acc[2][4][4];
#pragma unroll
    for (int m = 0; m < 2; m++)
#pragma unroll
        for (int nn = 0; nn < 4; nn++)
#pragma unroll
            for (int x = 0; x < 4; x++) acc[m][nn][x] = 0.0f;

    const int abase = g4 * PLANE + wid * 40 + g2 + 3;
    const int a2off = 4 * PLANE;

    stage(0, 0);
    stage(1, 1);

    for (int t = 0; t < NCH; t++) {
        if (t + 1 < NCH) asm volatile("cp.async.wait_group 1;\n" ::);
        else             asm volatile("cp.async.wait_group 0;\n" ::);
        __syncthreads();
        if (t + 2 < NCH) stage(t + 2, (t + 2) % 3);

        const uint* sif = si_p + (t % 3) * SI_W;
        const uint* sbf = sb_p + (t % 3) * CHUNK_W;
#pragma unroll
        for (int r = 0; r < (ONEROW ? 1 : 3); r++) {
#pragma unroll
            for (int q = 0; q < 3; q++) {
                const int tap = r * 3 + q;
                uint b[4][2];
#pragma unroll
                for (int nn = 0; nn < 4; nn++) {
                    uint2 v = *reinterpret_cast<const uint2*>(
                        sbf + ((tap * 4 + nn) * 32 + lane) * 2);
                    b[nn][0] = v.x;
                    b[nn][1] = v.y;
                }
#pragma unroll
                for (int m = 0; m < 2; m++) {
                    int ai = abase + r * 40 + q + m * 16;
                    uint a0 = sif[ai];
                    uint a1 = sif[ai + 8];
                    uint a2 = sif[ai + a2off];
                    uint a3 = sif[ai + a2off + 8];
#pragma unroll
                    for (int nn = 0; nn < 4; nn++)
                        mma_f16(acc[m][nn], a0, a1, a2, a3,
                                b[nn][0], b[nn][1]);
                }
            }
        }
    }

    // ---- epilogue ----
    // C fragment: c0,c1 = (oc, oc+1) at w = m*16+g2; c2,c3 = same at w+8.
    if (POOL) {
        __syncthreads();   // all warps done with arena before stash aliasing
#pragma unroll
        for (int m = 0; m < 2; m++)
#pragma unroll
            for (int nn = 0; nn < 4; nn++) {
                int ocp = nn * 4 + g4;
                int wl  = m * 16 + g2;
                sO[wid * (32 * 18) + wl * 18 + ocp] =
                    pack_h2(dlrelu(acc[m][nn][0]), dlrelu(acc[m][nn][1]));
                sO[wid * (32 * 18) + (wl + 8) * 18 + ocp] =
                    pack_h2(dlrelu(acc[m][nn][2]), dlrelu(acc[m][nn][3]));
            }
        __syncthreads();
        uint* out = (uint*)outv;
        const int C2out = OCG * 16;
        const int H2 = H >> 1, W2 = W >> 1;
        const int pw = tid & 15, ph = (tid >> 4) & 3, ob = tid >> 6;
#pragma unroll
        for (int k = 0; k < 4; k++) {
            int ocp = ob * 4 + k;
            const uint* s0 = sO + (2 * ph) * (32 * 18) + (2 * pw) * 18 + ocp;
            uint v = max_h2(max_h2(s0[0], s0[18]),
                            max_h2(s0[32 * 18], s0[32 * 18 + 18]));
            out[((size_t)(n * C2out + ocg * 16 + ocp) * H2 + (h0 >> 1) + ph) * W2
                + (w0 >> 1) + pw] = v;
        }
    } else if (FINAL) {
        float* out = (float*)outv;
        const int Cout = OCG * 32;
        const int h = h0 + wid;
#pragma unroll
        for (int m = 0; m < 2; m++) {
#pragma unroll
            for (int nn = 0; nn < 4; nn++) {
                int oc = ocg * 32 + nn * 8 + 2 * g4;
                int wv = w0 + m * 16 + g2;
                float* p0 = out + ((size_t)(n * Cout + oc) * H + h) * W + wv;
                float* p1 = p0 + (size_t)H * W;
                p0[0] = dlrelu(acc[m][nn][0]);
                p1[0] = dlrelu(acc[m][nn][1]);
                p0[8] = dlrelu(acc[m][nn][2]);
                p1[8] = dlrelu(acc[m][nn][3]);
            }
        }
    } else {
        uint* out = (uint*)outv;
        const int C2out = OCG * 16;
        const int h = h0 + wid;
#pragma unroll
        for (int m = 0; m < 2; m++) {
#pragma unroll
            for (int nn = 0; nn < 4; nn++) {
                int ocp = ocg * 16 + nn * 4 + g4;
                int wv  = w0 + m * 16 + g2;
                uint* p = out + ((size_t)(n * C2out + ocp) * H + h) * W + wv;
                p[0] = pack_h2(dlrelu(acc[m][nn][0]), dlrelu(acc[m][nn][1]));
                p[8] = pack_h2(dlrelu(acc[m][nn][2]), dlrelu(acc[m][nn][3]));
            }
        }
    }
}

// ---------------------------------------------------------------------------
extern "C" void kernel_launch(void* const* d_in, const int* in_sizes, int n_in,
                              void* d_out, int out_size)
{
    const float* x  = (const float*)d_in[0];
    const float* w1 = (const float*)d_in[1];
    const float* w2 = (const float*)d_in[2];
    const float* w3 = (const float*)d_in[3];
    const float* w4 = (const float*)d_in[4];
    const float* w5 = (const float*)d_in[5];
    const float* w6 = (const float*)d_in[6];

    uint *A, *B, *Wp;
    cudaGetSymbolAddress((void**)&A, g_bufA);
    cudaGetSymbolAddress((void**)&B, g_bufB);
    cudaGetSymbolAddress((void**)&Wp, g_bufW);

    const int o2 = 0, o3 = 4608, o4 = 13824, o5 = 32256, o6 = 44544;

    // Dynamic smem sizes (words -> bytes)
    const int SM_FULL = 3 * (8 * 424 + 9 * 256) * 4;   // 68352B (non-ONEROW)
    const int SM_ONE  = 3 * (8 * 328 + 3 * 256) * 4;   // 40704B (ONEROW)

    cudaFuncSetAttribute(conv3x3_mma<32, 0, 1, 0>,
                         cudaFuncAttributeMaxDynamicSharedMemorySize, SM_FULL);
    cudaFuncSetAttribute(conv3x3_mma<32, 0, 0, 0>,
                         cudaFuncAttributeMaxDynamicSharedMemorySize, SM_FULL);
    cudaFuncSetAttribute(conv3x3_mma<64, 0, 1, 0>,
                         cudaFuncAttributeMaxDynamicSharedMemorySize, SM_FULL);
    cudaFuncSetAttribute(conv3x3_mma<64, 1, 0, 0>,
                         cudaFuncAttributeMaxDynamicSharedMemorySize, SM_ONE);
    cudaFuncSetAttribute(conv3x3_mma<128, 1, 0, 1>,
                         cudaFuncAttributeMaxDynamicSharedMemorySize, SM_ONE);

    // Prep: fused fp16 round + pack of all conv weights (69120 words).
    pack_all<<<270, 256>>>(w2, w3, w4, w5, w6, Wp);

    // conv1: x [2,1,1024,256] fp32 -> A fp16 [2][16cp][1024][256]
    conv5x5_c1<<<dim3(4, 256, 2), 256>>>(x, w1, A);

    // conv2 (+pool1 fused): A -> B fp16 [2][16cp][512][128]
    conv3x3_mma<32, 0, 1, 0><<<dim3(8, 128, 2), 256, SM_FULL>>>(
        A, Wp + o2, B, 1024, 256, 512, 1);

    // conv3: B -> A fp16 [2][32cp][512][128] (sliceH=32)
    conv3x3_mma<32, 0, 0, 0><<<dim3(4, 64, 4), 256, SM_FULL>>>(
        B, Wp + o3, A, 512, 128, 32, 2);

    // conv4 (+pool2 fused): A -> B fp16 [2][32cp][256][64]
    conv3x3_mma<64, 0, 1, 0><<<dim3(4, 64, 4), 256, SM_FULL>>>(
        A, Wp + o4, B, 512, 128, 32, 2);

    // conv5: B -> A fp16 [2][64cp][256][64] (1x3 middle row)
    conv3x3_mma<64, 1, 0, 0><<<dim3(2, 32, 8), 256, SM_ONE>>>(
        B, Wp + o5, A, 256, 64, 1, 4);

    // conv6: A -> out fp32 NCHW [2,128,256,64] (final)
    conv3x3_mma<128, 1, 0, 1><<<dim3(2, 32, 8), 256, SM_ONE>>>(
        A, Wp + o6, d_out, 256, 64, 1, 4);
}

// round 12
// speedup vs baseline: 2.1481x; 1.0169x over previous
#include <cuda_runtime.h>
#include <cuda_fp16.h>

// ---------------------------------------------------------------------------
// FrameLevelPartFeatureExtractor — FP16 tensor-core (mma.sync m16n8k16) conv
// pipeline. Intermediates fp16 cpair-interleaved [N][C/2][H][W][2].
// conv2..conv6: implicit GEMM, block tile 8h x 64w x 32oc, warp = one h-row
// with M=64 x N=32 (16 mmas/tap -> 192B LDS per mma), 3-stage cp.async
// pipeline (1 sync/chunk), K-chunk = 16 cin. conv2/conv4 fuse 2x2 maxpool.
// conv1 packed-f32x2. Final conv6 writes fp32 NCHW.
// ---------------------------------------------------------------------------

typedef unsigned int uint;
typedef unsigned long long u64;

__device__ __align__(16) uint g_bufA[8388608];
__device__ __align__(16) uint g_bufB[8388608];
__device__ __align__(16) uint g_bufW[69120];   // packed fp16 weights, w2..w6

__device__ __forceinline__ float dlrelu(float v) {
    return v > 0.0f ? v : 0.01f * (0.01f * v);
}
__device__ __forceinline__ uint pack_h2(float lo, float hi) {
    uint r; asm("cvt.rn.f16x2.f32 %0, %1, %2;" : "=r"(r) : "f"(hi), "f"(lo));
    return r;
}
__device__ __forceinline__ uint max_h2(uint a, uint b) {
    uint r; asm("max.f16x2 %0, %1, %2;" : "=r"(r) : "r"(a), "r"(b));
    return r;
}
__device__ __forceinline__ void cp16(unsigned dst, const void* src, int sz) {
    asm volatile("cp.async.cg.shared.global [%0], [%1], 16, %2;\n"
                 :: "r"(dst), "l"(src), "r"(sz));
}
__device__ __forceinline__ void cp_commit() {
    asm volatile("cp.async.commit_group;\n" ::);
}
__device__ __forceinline__ void mma_f16(float* c, uint a0, uint a1, uint a2,
                                        uint a3, uint b0, uint b1) {
    asm volatile(
        "mma.sync.aligned.m16n8k16.row.col.f32.f16.f16.f32 "
        "{%0,%1,%2,%3}, {%4,%5,%6,%7}, {%8,%9}, {%0,%1,%2,%3};"
        : "+f"(c[0]), "+f"(c[1]), "+f"(c[2]), "+f"(c[3])
        : "r"(a0), "r"(a1), "r"(a2), "r"(a3), "r"(b0), "r"(b1));
}
__device__ __forceinline__ u64 dup_f(float v) {
    u64 r; asm("mov.b64 %0, {%1, %1};" : "=l"(r) : "f"(v)); return r;
}
__device__ __forceinline__ void ffma2(u64& d, u64 a, u64 b) {
    asm("fma.rn.f32x2 %0, %1, %2, %0;" : "+l"(d) : "l"(a), "l"(b));
}
__device__ __forceinline__ float2 unpk(u64 a) {
    float2 f; asm("mov.b64 {%0, %1}, %2;" : "=f"(f.x), "=f"(f.y) : "l"(a));
    return f;
}

// ---------------------------------------------------------------------------
// Fused fp16 weight pack for layers 2..6 (layout unchanged from R11).
// ---------------------------------------------------------------------------
__global__ void pack_all(const float* __restrict__ w2, const float* __restrict__ w3,
                         const float* __restrict__ w4, const float* __restrict__ w5,
                         const float* __restrict__ w6, uint* __restrict__ pk)
{
    int idx = blockIdx.x * blockDim.x + threadIdx.x;
    if (idx >= 69120) return;
    const float* w; int CIN, NCH, TAPS_, local;
    if (idx < 4608)       { w = w2; CIN = 32;  NCH = 2; TAPS_ = 9; local = idx; }
    else if (idx < 13824) { w = w3; CIN = 32;  NCH = 2; TAPS_ = 9; local = idx - 4608; }
    else if (idx < 32256) { w = w4; CIN = 64;  NCH = 4; TAPS_ = 9; local = idx - 13824; }
    else if (idx < 44544) { w = w5; CIN = 64;  NCH = 4; TAPS_ = 3; local = idx - 32256; }
    else                  { w = w6; CIN = 128; NCH = 8; TAPS_ = 3; local = idx - 44544; }
    int j    = local & 1;
    int r1   = local >> 1;
    int lane = r1 & 31;
    int r2   = r1 >> 5;
    int nn   = r2 & 3;
    int r3   = r2 >> 2;
    int tap  = r3 % TAPS_;
    int r4   = r3 / TAPS_;
    int t    = r4 % NCH;
    int ocg  = r4 / NCH;
    int oc   = ocg * 32 + nn * 8 + (lane >> 2);
    int cin  = t * 16 + 2 * ((lane & 3) + 4 * j);
    int tapIdx = (TAPS_ == 3) ? (tap + 3) : tap;
    float v0 = w[(oc * CIN + cin) * 9 + tapIdx];
    float v1 = w[(oc * CIN + cin + 1) * 9 + tapIdx];
    pk[idx] = pack_h2(v0, v1);
}

// ---------------------------------------------------------------------------
// conv1: 5x5, Cin=1, Cout=32, packed f32x2 FMA; fp16 cpair-interleaved out.
// ---------------------------------------------------------------------------
__global__ __launch_bounds__(256, 2)
void conv5x5_c1(const float* __restrict__ in, const float* __restrict__ wgt,
                uint* __restrict__ out)
{
    const int H = 1024, W = 256, SL = 512, TH = 4, TW = 64;
    const int n  = blockIdx.z;
    const int h0 = blockIdx.y * TH;
    const int w0 = blockIdx.x * TW;
    const int tid = threadIdx.x;
    const int op0 = (tid & 3) * 4;
    const int lw  = ((tid >> 2) & 15) * 4;
    const int hh  = tid >> 6;

    __shared__ float si[TH + 4][TW + 4];
    __shared__ float2 swp[16][25];

    for (int i = tid; i < 32 * 25; i += 256) {
        int o = i / 25, t = i % 25;
        float v = wgt[i];
        if (o & 1) swp[o >> 1][t].y = v; else swp[o >> 1][t].x = v;
    }

    const int ss = (h0 / SL) * SL, se = ss + SL;
    for (int i = tid; i < (TH + 4) * (TW + 4); i += 256) {
        int r = i / (TW + 4), c = i % (TW + 4);
        int g = h0 - 2 + r, gc = w0 - 2 + c;
        float v = 0.0f;
        if (g >= ss && g < se && gc >= 0 && gc < W)
            v = in[(n * H + g) * W + gc];
        si[r][c] = v;
    }
    __syncthreads();

    u64 dup[5][8];
#pragma unroll
    for (int r = 0; r < 5; r++)
#pragma unroll
        for (int c = 0; c < 8; c++)
            dup[r][c] = dup_f(si[hh + r][lw + c]);

    u64 acc[4][4];
#pragma unroll
    for (int p = 0; p < 4; p++)
#pragma unroll
        for (int x = 0; x < 4; x++) acc[p][x] = 0ULL;

#pragma unroll
    for (int p = 0; p < 4; p++) {
        const u64* wp = reinterpret_cast<const u64*>(&swp[op0 + p][0]);
#pragma unroll
        for (int r = 0; r < 5; r++)
#pragma unroll
            for (int kc = 0; kc < 5; kc++) {
                u64 wv = wp[r * 5 + kc];
#pragma unroll
                for (int x = 0; x < 4; x++)
                    ffma2(acc[p][x], dup[r][kc + x], wv);
            }
    }

#pragma unroll
    for (int p = 0; p < 4; p++) {
        uint4 st;
        uint* sv = &st.x;
#pragma unroll
        for (int x = 0; x < 4; x++) {
            float2 f = unpk(acc[p][x]);
            sv[x] = pack_h2(dlrelu(f.x), dlrelu(f.y));
        }
        int ocp = (tid & 3) * 4 + p;          // channel-pair index (0..15)
        uint* op = &out[(((size_t)n * 16 + ocp) * H + h0 + hh) * W + w0 + lw];
        *reinterpret_cast<uint4*>(op) = st;
    }
}

// ---------------------------------------------------------------------------
// FP16 implicit-GEMM 3x3 focal conv, 3-stage pipeline (1 sync/chunk).
// Block tile: 8h x 64w x 32oc, warp = one h row, M=64 (4 m-subtiles) x N=32.
// K-chunk = 16 cin (8 cpair planes; word = half2 of adjacent cins).
// ONEROW: sliceH==1 -> 1x3 conv, middle weight row, no h-halo.
// POOL: fused 2x2 maxpool epilogue (stash aliases dead arena).
// FINAL: fp32 plain-NCHW output.
// ---------------------------------------------------------------------------
template <int CIN, int ONEROW, int POOL, int FINAL>
__global__ __launch_bounds__(256, 2)
void conv3x3_mma(const uint* __restrict__ in, const uint* __restrict__ pk,
                 void* __restrict__ outv, int H, int W, int sliceH, int OCG)
{
    constexpr int TH    = 8;
    constexpr int ROWS  = ONEROW ? TH : (TH + 2);
    constexpr int TAPS  = ONEROW ? 3 : 9;
    constexpr int PLANE = ONEROW ? 584 : 744;   // >=ROWS*72, ==8 mod 32, /4
    constexpr int SI_W  = 8 * PLANE;            // 8 cpair planes
    constexpr int CHUNK_W = TAPS * 256;
    constexpr int NCH   = CIN / 16;
    constexpr int NROWOPS = 8 * ROWS * 18;      // 18 cp16 per row
    constexpr int NI    = (NROWOPS + 255) / 256;
    constexpr int NWOPS = TAPS * 64;
    constexpr int NW    = (NWOPS + 255) / 256;
    constexpr int ARENA = 3 * (SI_W + CHUNK_W);

    static_assert(!POOL || ARENA >= TH * 64 * 18, "pool stash fits");
    static_assert(NCH >= 2, "pipeline needs >= 2 chunks");

    extern __shared__ __align__(16) uint arena[];
    uint* si_p = arena;
    uint* sb_p = arena + 3 * SI_W;
    uint* sO   = arena;

    const int z    = blockIdx.z;
    const int ocg  = z % OCG;
    const int n    = z / OCG;
    const int h0   = blockIdx.y * TH;
    const int w0   = blockIdx.x * 64;
    const int tid  = threadIdx.x;
    const int lane = tid & 31;
    const int wid  = tid >> 5;      // h row within tile
    const int g2 = lane >> 2;
    const int g4 = lane & 3;

    const int ss = ONEROW ? 0 : (h0 / sliceH) * sliceH;
    const int se = ss + sliceH;

    const int C2in = CIN / 2;
    const uint* base = in + (size_t)n * C2in * H * W;
    const uint* pk0  = pk + (size_t)(ocg * NCH) * CHUNK_W;

    // ---- hoisted input staging descriptors (all cp16) ----
    // Row covers words w0-4 .. w0+67 (18 granules of 4 words). Granules are
    // fully-valid or fully-OOB (W multiple of 4, w0 multiple of 64).
    int di_dst[NI], di_off[NI];
#pragma unroll
    for (int k = 0; k < NI; k++) {
        int i = tid + k * 256;
        int dst = -1, off = -1;
        if (i < NROWOPS) {
            int rowid = i / 18, sub = i - rowid * 18;
            int c = rowid / ROWS, r = rowid - c * ROWS;   // c = cpair 0..7
            int g = ONEROW ? (h0 + r) : (h0 - 1 + r);
            bool rowok = ONEROW ? true : (g >= ss && g < se);
            int gc = w0 - 4 + sub * 4;
            dst = (c * PLANE + r * 72 + sub * 4) * 4;
            off = (rowok && gc >= 0 && gc < W) ? ((c * H + g) * W + gc) : -1;
        }
        di_dst[k] = dst; di_off[k] = off;
    }

    unsigned si_s = (unsigned)__cvta_generic_to_shared(si_p);
    unsigned sb_s = (unsigned)__cvta_generic_to_shared(sb_p);

    auto stage = [&](int t, int buf) {
        const uint* cb = base + (size_t)t * 8 * H * W;   // 8 cpairs per chunk
        unsigned sd = si_s + (unsigned)buf * (SI_W * 4);
#pragma unroll
        for (int k = 0; k < NI; k++) {
            int d = di_dst[k];
            if (d >= 0) {
                int off = di_off[k];
                cp16(sd + (unsigned)d,
                     off >= 0 ? (const void*)(cb + off) : (const void*)cb,
                     off >= 0 ? 16 : 0);
            }
        }
        const uint* wb = pk0 + (size_t)t * CHUNK_W;
        unsigned wd = sb_s + (unsigned)buf * (CHUNK_W * 4);
#pragma unroll
        for (int k = 0; k < NW; k++) {
            int i = tid + k * 256;
            if (NWOPS % 256 == 0 || i < NWOPS)
                cp16(wd + (unsigned)i * 16, wb + i * 4, 16);
        }
        cp_commit();
    };

    float acc[4][4][4];
#pragma unroll
    for (int m = 0; m < 4; m++)
#pragma unroll
        for (int nn = 0; nn < 4; nn++)
#pragma unroll
            for (int x = 0; x < 4; x++) acc[m][nn][x] = 0.0f;

    const int abase = g4 * PLANE + wid * 72 + g2 + 3;
    const int a2off = 4 * PLANE;

    stage(0, 0);
    stage(1, 1);

    for (int t = 0; t < NCH; t++) {
        if (t + 1 < NCH) asm volatile("cp.async.wait_group 1;\n" ::);
        else             asm volatile("cp.async.wait_group 0;\n" ::);
        __syncthreads();
        if (t + 2 < NCH) stage(t + 2, (t + 2) % 3);

        const uint* sif = si_p + (t % 3) * SI_W;
        const uint* sbf = sb_p + (t % 3) * CHUNK_W;
#pragma unroll
        for (int r = 0; r < (ONEROW ? 1 : 3); r++) {
#pragma unroll
            for (int q = 0; q < 3; q++) {
                const int tap = r * 3 + q;
                uint b[4][2];
#pragma unroll
                for (int nn = 0; nn < 4; nn++) {
                    uint2 v = *reinterpret_cast<const uint2*>(
                        sbf + ((tap * 4 + nn) * 32 + lane) * 2);
                    b[nn][0] = v.x;
                    b[nn][1] = v.y;
                }
#pragma unroll
                for (int m = 0; m < 4; m++) {
                    int ai = abase + r * 72 + q + m * 16;
                    uint a0 = sif[ai];
                    uint a1 = sif[ai + 8];
                    uint a2 = sif[ai + a2off];
                    uint a3 = sif[ai + a2off + 8];
#pragma unroll
                    for (int nn = 0; nn < 4; nn++)
                        mma_f16(acc[m][nn], a0, a1, a2, a3,
                                b[nn][0], b[nn][1]);
                }
            }
        }
    }

    // ---- epilogue ----
    // C fragment: c0,c1 = (oc, oc+1) at w = m*16+g2; c2,c3 = same at w+8.
    if (POOL) {
        __syncthreads();   // all warps done with arena before stash aliasing
#pragma unroll
        for (int m = 0; m < 4; m++)
#pragma unroll
            for (int nn = 0; nn < 4; nn++) {
                int ocp = nn * 4 + g4;
                int wl  = m * 16 + g2;
                sO[wid * (64 * 18) + wl * 18 + ocp] =
                    pack_h2(dlrelu(acc[m][nn][0]), dlrelu(acc[m][nn][1]));
                sO[wid * (64 * 18) + (wl + 8) * 18 + ocp] =
                    pack_h2(dlrelu(acc[m][nn][2]), dlrelu(acc[m][nn][3]));
            }
        __syncthreads();
        uint* out = (uint*)outv;
        const int C2out = OCG * 16;
        const int H2 = H >> 1, W2 = W >> 1;
        const int pw = tid & 31, ph = (tid >> 5) & 3, ob = tid >> 7;
#pragma unroll
        for (int k = 0; k < 8; k++) {
            int ocp = ob * 8 + k;
            const uint* s0 = sO + (2 * ph) * (64 * 18) + (2 * pw) * 18 + ocp;
            uint v = max_h2(max_h2(s0[0], s0[18]),
                            max_h2(s0[64 * 18], s0[64 * 18 + 18]));
            out[((size_t)(n * C2out + ocg * 16 + ocp) * H2 + (h0 >> 1) + ph) * W2
                + (w0 >> 1) + pw] = v;
        }
    } else if (FINAL) {
        float* out = (float*)outv;
        const int Cout = OCG * 32;
        const int h = h0 + wid;
#pragma unroll
        for (int m = 0; m < 4; m++) {
#pragma unroll
            for (int nn = 0; nn < 4; nn++) {
                int oc = ocg * 32 + nn * 8 + 2 * g4;
                int wv = w0 + m * 16 + g2;
                float* p0 = out + ((size_t)(n * Cout + oc) * H + h) * W + wv;
                float* p1 = p0 + (size_t)H * W;
                p0[0] = dlrelu(acc[m][nn][0]);
                p1[0] = dlrelu(acc[m][nn][1]);
                p0[8] = dlrelu(acc[m][nn][2]);
                p1[8] = dlrelu(acc[m][nn][3]);
            }
        }
    } else {
        uint* out = (uint*)outv;
        const int C2out = OCG * 16;
        const int h = h0 + wid;
#pragma unroll
        for (int m = 0; m < 4; m++) {
#pragma unroll
            for (int nn = 0; nn < 4; nn++) {
                int ocp = ocg * 16 + nn * 4 + g4;
                int wv  = w0 + m * 16 + g2;
                uint* p = out + ((size_t)(n * C2out + ocp) * H + h) * W + wv;
                p[0] = pack_h2(dlrelu(acc[m][nn][0]), dlrelu(acc[m][nn][1]));
                p[8] = pack_h2(dlrelu(acc[m][nn][2]), dlrelu(acc[m][nn][3]));
            }
        }
    }
}

// ---------------------------------------------------------------------------
extern "C" void kernel_launch(void* const* d_in, const int* in_sizes, int n_in,
                              void* d_out, int out_size)
{
    const float* x  = (const float*)d_in[0];
    const float* w1 = (const float*)d_in[1];
    const float* w2 = (const float*)d_in[2];
    const float* w3 = (const float*)d_in[3];
    const float* w4 = (const float*)d_in[4];
    const float* w5 = (const float*)d_in[5];
    const float* w6 = (const float*)d_in[6];

    uint *A, *B, *Wp;
    cudaGetSymbolAddress((void**)&A, g_bufA);
    cudaGetSymbolAddress((void**)&B, g_bufB);
    cudaGetSymbolAddress((void**)&Wp, g_bufW);

    const int o2 = 0, o3 = 4608, o4 = 13824, o5 = 32256, o6 = 44544;

    // Dynamic smem sizes (words -> bytes)
    const int SM_FULL = 3 * (8 * 744 + 9 * 256) * 4;   // 99072B
    const int SM_ONE  = 3 * (8 * 584 + 3 * 256) * 4;   // 65280B

    cudaFuncSetAttribute(conv3x3_mma<32, 0, 1, 0>,
                         cudaFuncAttributeMaxDynamicSharedMemorySize, SM_FULL);
    cudaFuncSetAttribute(conv3x3_mma<32, 0, 0, 0>,
                         cudaFuncAttributeMaxDynamicSharedMemorySize, SM_FULL);
    cudaFuncSetAttribute(conv3x3_mma<64, 0, 1, 0>,
                         cudaFuncAttributeMaxDynamicSharedMemorySize, SM_FULL);
    cudaFuncSetAttribute(conv3x3_mma<64, 1, 0, 0>,
                         cudaFuncAttributeMaxDynamicSharedMemorySize, SM_ONE);
    cudaFuncSetAttribute(conv3x3_mma<128, 1, 0, 1>,
                         cudaFuncAttributeMaxDynamicSharedMemorySize, SM_ONE);

    // Prep: fused fp16 round + pack of all conv weights (69120 words).
    pack_all<<<270, 256>>>(w2, w3, w4, w5, w6, Wp);

    // conv1: x [2,1,1024,256] fp32 -> A fp16 [2][16cp][1024][256]
    conv5x5_c1<<<dim3(4, 256, 2), 256>>>(x, w1, A);

    // conv2 (+pool1 fused): A -> B fp16 [2][16cp][512][128]
    conv3x3_mma<32, 0, 1, 0><<<dim3(4, 128, 2), 256, SM_FULL>>>(
        A, Wp + o2, B, 1024, 256, 512, 1);

    // conv3: B -> A fp16 [2][32cp][512][128] (sliceH=32)
    conv3x3_mma<32, 0, 0, 0><<<dim3(2, 64, 4), 256, SM_FULL>>>(
        B, Wp + o3, A, 512, 128, 32, 2);

    // conv4 (+pool2 fused): A -> B fp16 [2][32cp][256][64]
    conv3x3_mma<64, 0, 1, 0><<<dim3(2, 64, 4), 256, SM_FULL>>>(
        A, Wp + o4, B, 512, 128, 32, 2);

    // conv5: B -> A fp16 [2][64cp][256][64] (1x3 middle row)
    conv3x3_mma<64, 1, 0, 0><<<dim3(1, 32, 8), 256, SM_ONE>>>(
        B, Wp + o5, A, 256, 64, 1, 4);

    // conv6: A -> out fp32 NCHW [2,128,256,64] (final)
    conv3x3_mma<128, 1, 0, 1><<<dim3(1, 32, 8), 256, SM_ONE>>>(
        A, Wp + o6, d_out, 256, 64, 1, 4);
}

// round 13
// speedup vs baseline: 2.1816x; 1.0156x over previous
#include <cuda_runtime.h>
#include <cuda_fp16.h>

// ---------------------------------------------------------------------------
// FrameLevelPartFeatureExtractor — FP16 tensor-core (mma.sync m16n8k16) conv
// pipeline. Intermediates fp16 cpair-interleaved [N][C/2][H][W][2].
// conv2..conv6: implicit GEMM, block tile 8h x 64w x 32oc, warp = one h-row
// with M=64 x N=32, 3-stage cp.async pipeline (1 sync/chunk), K-chunk=16 cin.
// conv2/conv4 fuse 2x2 maxpool. conv1 packed-f32x2 AND folds the weight-pack
// prep (first 270 blocks). Final conv6 writes fp32 NCHW.
// ---------------------------------------------------------------------------

typedef unsigned int uint;
typedef unsigned long long u64;

__device__ __align__(16) uint g_bufA[8388608];
__device__ __align__(16) uint g_bufB[8388608];
__device__ __align__(16) uint g_bufW[69120];   // packed fp16 weights, w2..w6

__device__ __forceinline__ float dlrelu(float v) {
    return v > 0.0f ? v : 0.01f * (0.01f * v);
}
__device__ __forceinline__ uint pack_h2(float lo, float hi) {
    uint r; asm("cvt.rn.f16x2.f32 %0, %1, %2;" : "=r"(r) : "f"(hi), "f"(lo));
    return r;
}
__device__ __forceinline__ uint max_h2(uint a, uint b) {
    uint r; asm("max.f16x2 %0, %1, %2;" : "=r"(r) : "r"(a), "r"(b));
    return r;
}
__device__ __forceinline__ void cp16(unsigned dst, const void* src, int sz) {
    asm volatile("cp.async.cg.shared.global [%0], [%1], 16, %2;\n"
                 :: "r"(dst), "l"(src), "r"(sz));
}
__device__ __forceinline__ void cp_commit() {
    asm volatile("cp.async.commit_group;\n" ::);
}
__device__ __forceinline__ void mma_f16(float* c, uint a0, uint a1, uint a2,
                                        uint a3, uint b0, uint b1) {
    asm volatile(
        "mma.sync.aligned.m16n8k16.row.col.f32.f16.f16.f32 "
        "{%0,%1,%2,%3}, {%4,%5,%6,%7}, {%8,%9}, {%0,%1,%2,%3};"
        : "+f"(c[0]), "+f"(c[1]), "+f"(c[2]), "+f"(c[3])
        : "r"(a0), "r"(a1), "r"(a2), "r"(a3), "r"(b0), "r"(b1));
}
__device__ __forceinline__ u64 dup_f(float v) {
    u64 r; asm("mov.b64 %0, {%1, %1};" : "=l"(r) : "f"(v)); return r;
}
__device__ __forceinline__ void ffma2(u64& d, u64 a, u64 b) {
    asm("fma.rn.f32x2 %0, %1, %2, %0;" : "+l"(d) : "l"(a), "l"(b));
}
__device__ __forceinline__ float2 unpk(u64 a) {
    float2 f; asm("mov.b64 {%0, %1}, %2;" : "=f"(f.x), "=f"(f.y) : "l"(a));
    return f;
}

// ---------------------------------------------------------------------------
// conv1: 5x5, Cin=1, Cout=32, packed f32x2 FMA; fp16 cpair-interleaved out.
// ALSO: first 270 blocks fold in the fp16 weight pack for layers 2..6
// (69120 words; layout identical to R11/R12 pack_all).
// ---------------------------------------------------------------------------
__global__ __launch_bounds__(256, 2)
void conv5x5_c1(const float* __restrict__ in, const float* __restrict__ wgt,
                uint* __restrict__ out,
                const float* __restrict__ w2, const float* __restrict__ w3,
                const float* __restrict__ w4, const float* __restrict__ w5,
                const float* __restrict__ w6, uint* __restrict__ pk)
{
    const int H = 1024, W = 256, SL = 512, TH = 4, TW = 64;
    const int n  = blockIdx.z;
    const int h0 = blockIdx.y * TH;
    const int w0 = blockIdx.x * TW;
    const int tid = threadIdx.x;
    const int op0 = (tid & 3) * 4;
    const int lw  = ((tid >> 2) & 15) * 4;
    const int hh  = tid >> 6;

    __shared__ float si[TH + 4][TW + 4];
    __shared__ float2 swp[16][25];

    for (int i = tid; i < 32 * 25; i += 256) {
        int o = i / 25, t = i % 25;
        float v = wgt[i];
        if (o & 1) swp[o >> 1][t].y = v; else swp[o >> 1][t].x = v;
    }

    const int ss = (h0 / SL) * SL, se = ss + SL;
    for (int i = tid; i < (TH + 4) * (TW + 4); i += 256) {
        int r = i / (TW + 4), c = i % (TW + 4);
        int g = h0 - 2 + r, gc = w0 - 2 + c;
        float v = 0.0f;
        if (g >= ss && g < se && gc >= 0 && gc < W)
            v = in[(n * H + g) * W + gc];
        si[r][c] = v;
    }
    __syncthreads();

    u64 dup[5][8];
#pragma unroll
    for (int r = 0; r < 5; r++)
#pragma unroll
        for (int c = 0; c < 8; c++)
            dup[r][c] = dup_f(si[hh + r][lw + c]);

    u64 acc[4][4];
#pragma unroll
    for (int p = 0; p < 4; p++)
#pragma unroll
        for (int x = 0; x < 4; x++) acc[p][x] = 0ULL;

#pragma unroll
    for (int p = 0; p < 4; p++) {
        const u64* wp = reinterpret_cast<const u64*>(&swp[op0 + p][0]);
#pragma unroll
        for (int r = 0; r < 5; r++)
#pragma unroll
            for (int kc = 0; kc < 5; kc++) {
                u64 wv = wp[r * 5 + kc];
#pragma unroll
                for (int x = 0; x < 4; x++)
                    ffma2(acc[p][x], dup[r][kc + x], wv);
            }
    }

#pragma unroll
    for (int p = 0; p < 4; p++) {
        uint4 st;
        uint* sv = &st.x;
#pragma unroll
        for (int x = 0; x < 4; x++) {
            float2 f = unpk(acc[p][x]);
            sv[x] = pack_h2(dlrelu(f.x), dlrelu(f.y));
        }
        int ocp = (tid & 3) * 4 + p;          // channel-pair index (0..15)
        uint* op = &out[(((size_t)n * 16 + ocp) * H + h0 + hh) * W + w0 + lw];
        *reinterpret_cast<uint4*>(op) = st;
    }

    // ---- folded weight pack (first 270 blocks; 270*256 = 69120 exactly) ----
    {
        int bid = (blockIdx.z * gridDim.y + blockIdx.y) * gridDim.x + blockIdx.x;
        if (bid < 270) {
            int idx = bid * 256 + tid;
            const float* w; int CIN, NCH, TAPS_, local;
            if (idx < 4608)       { w = w2; CIN = 32;  NCH = 2; TAPS_ = 9; local = idx; }
            else if (idx < 13824) { w = w3; CIN = 32;  NCH = 2; TAPS_ = 9; local = idx - 4608; }
            else if (idx < 32256) { w = w4; CIN = 64;  NCH = 4; TAPS_ = 9; local = idx - 13824; }
            else if (idx < 44544) { w = w5; CIN = 64;  NCH = 4; TAPS_ = 3; local = idx - 32256; }
            else                  { w = w6; CIN = 128; NCH = 8; TAPS_ = 3; local = idx - 44544; }
            int j    = local & 1;
            int r1   = local >> 1;
            int lane = r1 & 31;
            int r2   = r1 >> 5;
            int nn   = r2 & 3;
            int r3   = r2 >> 2;
            int tap  = r3 % TAPS_;
            int r4   = r3 / TAPS_;
            int t    = r4 % NCH;
            int ocg  = r4 / NCH;
            int oc   = ocg * 32 + nn * 8 + (lane >> 2);
            int cin  = t * 16 + 2 * ((lane & 3) + 4 * j);
            int tapIdx = (TAPS_ == 3) ? (tap + 3) : tap;
            float v0 = w[(oc * CIN + cin) * 9 + tapIdx];
            float v1 = w[(oc * CIN + cin + 1) * 9 + tapIdx];
            pk[idx] = pack_h2(v0, v1);
        }
    }
}

// ---------------------------------------------------------------------------
// FP16 implicit-GEMM 3x3 focal conv, 3-stage pipeline (1 sync/chunk).
// Block tile: 8h x 64w x 32oc, warp = one h row, M=64 (4 m-subtiles) x N=32.
// K-chunk = 16 cin (8 cpair planes; word = half2 of adjacent cins).
// ONEROW: sliceH==1 -> 1x3 conv, middle weight row, no h-halo; all B
// fragments preloaded before the tap loop (ILP).
// POOL: fused 2x2 maxpool epilogue (stash aliases dead arena).
// FINAL: fp32 plain-NCHW output.
// ---------------------------------------------------------------------------
template <int CIN, int ONEROW, int POOL, int FINAL>
__global__ __launch_bounds__(256, 2)
void conv3x3_mma(const uint* __restrict__ in, const uint* __restrict__ pk,
                 void* __restrict__ outv, int H, int W, int sliceH, int OCG)
{
    constexpr int TH    = 8;
    constexpr int ROWS  = ONEROW ? TH : (TH + 2);
    constexpr int TAPS  = ONEROW ? 3 : 9;
    constexpr int PLANE = ONEROW ? 584 : 744;   // >=ROWS*72, ==8 mod 32, /4
    constexpr int SI_W  = 8 * PLANE;            // 8 cpair planes
    constexpr int CHUNK_W = TAPS * 256;
    constexpr int NCH   = CIN / 16;
    constexpr int NROWOPS = 8 * ROWS * 18;      // 18 cp16 per row
    constexpr int NI    = (NROWOPS + 255) / 256;
    constexpr int NWOPS = TAPS * 64;
    constexpr int NW    = (NWOPS + 255) / 256;
    constexpr int ARENA = 3 * (SI_W + CHUNK_W);

    static_assert(!POOL || ARENA >= TH * 64 * 18, "pool stash fits");
    static_assert(NCH >= 2, "pipeline needs >= 2 chunks");

    extern __shared__ __align__(16) uint arena[];
    uint* si_p = arena;
    uint* sb_p = arena + 3 * SI_W;
    uint* sO   = arena;

    const int z    = blockIdx.z;
    const int ocg  = z % OCG;
    const int n    = z / OCG;
    const int h0   = blockIdx.y * TH;
    const int w0   = blockIdx.x * 64;
    const int tid  = threadIdx.x;
    const int lane = tid & 31;
    const int wid  = tid >> 5;      // h row within tile
    const int g2 = lane >> 2;
    const int g4 = lane & 3;

    const int ss = ONEROW ? 0 : (h0 / sliceH) * sliceH;
    const int se = ss + sliceH;

    const int C2in = CIN / 2;
    const uint* base = in + (size_t)n * C2in * H * W;
    const uint* pk0  = pk + (size_t)(ocg * NCH) * CHUNK_W;

    // ---- hoisted input staging descriptors (all cp16) ----
    int di_dst[NI], di_off[NI];
#pragma unroll
    for (int k = 0; k < NI; k++) {
        int i = tid + k * 256;
        int dst = -1, off = -1;
        if (i < NROWOPS) {
            int rowid = i / 18, sub = i - rowid * 18;
            int c = rowid / ROWS, r = rowid - c * ROWS;   // c = cpair 0..7
            int g = ONEROW ? (h0 + r) : (h0 - 1 + r);
            bool rowok = ONEROW ? true : (g >= ss && g < se);
            int gc = w0 - 4 + sub * 4;
            dst = (c * PLANE + r * 72 + sub * 4) * 4;
            off = (rowok && gc >= 0 && gc < W) ? ((c * H + g) * W + gc) : -1;
        }
        di_dst[k] = dst; di_off[k] = off;
    }

    unsigned si_s = (unsigned)__cvta_generic_to_shared(si_p);
    unsigned sb_s = (unsigned)__cvta_generic_to_shared(sb_p);

    auto stage = [&](int t, int buf) {
        const uint* cb = base + (size_t)t * 8 * H * W;   // 8 cpairs per chunk
        unsigned sd = si_s + (unsigned)buf * (SI_W * 4);
#pragma unroll
        for (int k = 0; k < NI; k++) {
            int d = di_dst[k];
            if (d >= 0) {
                int off = di_off[k];
                cp16(sd + (unsigned)d,
                     off >= 0 ? (const void*)(cb + off) : (const void*)cb,
                     off >= 0 ? 16 : 0);
            }
        }
        const uint* wb = pk0 + (size_t)t * CHUNK_W;
        unsigned wd = sb_s + (unsigned)buf * (CHUNK_W * 4);
#pragma unroll
        for (int k = 0; k < NW; k++) {
            int i = tid + k * 256;
            if (NWOPS % 256 == 0 || i < NWOPS)
                cp16(wd + (unsigned)i * 16, wb + i * 4, 16);
        }
        cp_commit();
    };

    float acc[4][4][4];
#pragma unroll
    for (int m = 0; m < 4; m++)
#pragma unroll
        for (int nn = 0; nn < 4; nn++)
#pragma unroll
            for (int x = 0; x < 4; x++) acc[m][nn][x] = 0.0f;

    const int abase = g4 * PLANE + wid * 72 + g2 + 3;
    const int a2off = 4 * PLANE;

    stage(0, 0);
    stage(1, 1);

    for (int t = 0; t < NCH; t++) {
        if (t + 1 < NCH) asm volatile("cp.async.wait_group 1;\n" ::);
        else             asm volatile("cp.async.wait_group 0;\n" ::);
        __syncthreads();
        if (t + 2 < NCH) stage(t + 2, (t + 2) % 3);

        const uint* sif = si_p + (t % 3) * SI_W;
        const uint* sbf = sb_p + (t % 3) * CHUNK_W;

        if (ONEROW) {
            // Preload ALL taps' B fragments (3*4*2 = 24 regs) for ILP.
            uint ball[3][4][2];
#pragma unroll
            for (int q = 0; q < 3; q++)
#pragma unroll
                for (int nn = 0; nn < 4; nn++) {
                    uint2 v = *reinterpret_cast<const uint2*>(
                        sbf + ((q * 4 + nn) * 32 + lane) * 2);
                    ball[q][nn][0] = v.x;
                    ball[q][nn][1] = v.y;
                }
#pragma unroll
            for (int q = 0; q < 3; q++) {
#pragma unroll
                for (int m = 0; m < 4; m++) {
                    int ai = abase + q + m * 16;
                    uint a0 = sif[ai];
                    uint a1 = sif[ai + 8];
                    uint a2 = sif[ai + a2off];
                    uint a3 = sif[ai + a2off + 8];
#pragma unroll
                    for (int nn = 0; nn < 4; nn++)
                        mma_f16(acc[m][nn], a0, a1, a2, a3,
                                ball[q][nn][0], ball[q][nn][1]);
                }
            }
        } else {
#pragma unroll
            for (int r = 0; r < 3; r++) {
#pragma unroll
                for (int q = 0; q < 3; q++) {
                    const int tap = r * 3 + q;
                    uint b[4][2];
#pragma unroll
                    for (int nn = 0; nn < 4; nn++) {
                        uint2 v = *reinterpret_cast<const uint2*>(
                            sbf + ((tap * 4 + nn) * 32 + lane) * 2);
                        b[nn][0] = v.x;
                        b[nn][1] = v.y;
                    }
#pragma unroll
                    for (int m = 0; m < 4; m++) {
                        int ai = abase + r * 72 + q + m * 16;
                        uint a0 = sif[ai];
                        uint a1 = sif[ai + 8];
                        uint a2 = sif[ai + a2off];
                        uint a3 = sif[ai + a2off + 8];
#pragma unroll
                        for (int nn = 0; nn < 4; nn++)
                            mma_f16(acc[m][nn], a0, a1, a2, a3,
                                    b[nn][0], b[nn][1]);
                    }
                }
            }
        }
    }

    // ---- epilogue ----
    // C fragment: c0,c1 = (oc, oc+1) at w = m*16+g2; c2,c3 = same at w+8.
    if (POOL) {
        __syncthreads();   // all warps done with arena before stash aliasing
#pragma unroll
        for (int m = 0; m < 4; m++)
#pragma unroll
            for (int nn = 0; nn < 4; nn++) {
                int ocp = nn * 4 + g4;
                int wl  = m * 16 + g2;
                sO[wid * (64 * 18) + wl * 18 + ocp] =
                    pack_h2(dlrelu(acc[m][nn][0]), dlrelu(acc[m][nn][1]));
                sO[wid * (64 * 18) + (wl + 8) * 18 + ocp] =
                    pack_h2(dlrelu(acc[m][nn][2]), dlrelu(acc[m][nn][3]));
            }
        __syncthreads();
        uint* out = (uint*)outv;
        const int C2out = OCG * 16;
        const int H2 = H >> 1, W2 = W >> 1;
        const int pw = tid & 31, ph = (tid >> 5) & 3, ob = tid >> 7;
#pragma unroll
        for (int k = 0; k < 8; k++) {
            int ocp = ob * 8 + k;
            const uint* s0 = sO + (2 * ph) * (64 * 18) + (2 * pw) * 18 + ocp;
            uint v = max_h2(max_h2(s0[0], s0[18]),
                            max_h2(s0[64 * 18], s0[64 * 18 + 18]));
            out[((size_t)(n * C2out + ocg * 16 + ocp) * H2 + (h0 >> 1) + ph) * W2
                + (w0 >> 1) + pw] = v;
        }
    } else if (FINAL) {
        float* out = (float*)outv;
        const int Cout = OCG * 32;
        const int h = h0 + wid;
#pragma unroll
        for (int m = 0; m < 4; m++) {
#pragma unroll
            for (int nn = 0; nn < 4; nn++) {
                int oc = ocg * 32 + nn * 8 + 2 * g4;
                int wv = w0 + m * 16 + g2;
                float* p0 = out + ((size_t)(n * Cout + oc) * H + h) * W + wv;
                float* p1 = p0 + (size_t)H * W;
                p0[0] = dlrelu(acc[m][nn][0]);
                p1[0] = dlrelu(acc[m][nn][1]);
                p0[8] = dlrelu(acc[m][nn][2]);
                p1[8] = dlrelu(acc[m][nn][3]);
            }
        }
    } else {
        uint* out = (uint*)outv;
        const int C2out = OCG * 16;
        const int h = h0 + wid;
#pragma unroll
        for (int m = 0; m < 4; m++) {
#pragma unroll
            for (int nn = 0; nn < 4; nn++) {
                int ocp = ocg * 16 + nn * 4 + g4;
                int wv  = w0 + m * 16 + g2;
                uint* p = out + ((size_t)(n * C2out + ocp) * H + h) * W + wv;
                p[0] = pack_h2(dlrelu(acc[m][nn][0]), dlrelu(acc[m][nn][1]));
                p[8] = pack_h2(dlrelu(acc[m][nn][2]), dlrelu(acc[m][nn][3]));
            }
        }
    }
}

// ---------------------------------------------------------------------------
extern "C" void kernel_launch(void* const* d_in, const int* in_sizes, int n_in,
                              void* d_out, int out_size)
{
    const float* x  = (const float*)d_in[0];
    const float* w1 = (const float*)d_in[1];
    const float* w2 = (const float*)d_in[2];
    const float* w3 = (const float*)d_in[3];
    const float* w4 = (const float*)d_in[4];
    const float* w5 = (const float*)d_in[5];
    const float* w6 = (const float*)d_in[6];

    uint *A, *B, *Wp;
    cudaGetSymbolAddress((void**)&A, g_bufA);
    cudaGetSymbolAddress((void**)&B, g_bufB);
    cudaGetSymbolAddress((void**)&Wp, g_bufW);

    const int o2 = 0, o3 = 4608, o4 = 13824, o5 = 32256, o6 = 44544;

    // Dynamic smem sizes (words -> bytes)
    const int SM_FULL = 3 * (8 * 744 + 9 * 256) * 4;   // 99072B
    const int SM_ONE  = 3 * (8 * 584 + 3 * 256) * 4;   // 65280B

    cudaFuncSetAttribute(conv3x3_mma<32, 0, 1, 0>,
                         cudaFuncAttributeMaxDynamicSharedMemorySize, SM_FULL);
    cudaFuncSetAttribute(conv3x3_mma<32, 0, 0, 0>,
                         cudaFuncAttributeMaxDynamicSharedMemorySize, SM_FULL);
    cudaFuncSetAttribute(conv3x3_mma<64, 0, 1, 0>,
                         cudaFuncAttributeMaxDynamicSharedMemorySize, SM_FULL);
    cudaFuncSetAttribute(conv3x3_mma<64, 1, 0, 0>,
                         cudaFuncAttributeMaxDynamicSharedMemorySize, SM_ONE);
    cudaFuncSetAttribute(conv3x3_mma<128, 1, 0, 1>,
                         cudaFuncAttributeMaxDynamicSharedMemorySize, SM_ONE);

    // conv1 (+folded weight pack): x -> A fp16 [2][16cp][1024][256]
    conv5x5_c1<<<dim3(4, 256, 2), 256>>>(x, w1, A, w2, w3, w4, w5, w6, Wp);

    // conv2 (+pool1 fused): A -> B fp16 [2][16cp][512][128]
    conv3x3_mma<32, 0, 1, 0><<<dim3(4, 128, 2), 256, SM_FULL>>>(
        A, Wp + o2, B, 1024, 256, 512, 1);

    // conv3: B -> A fp16 [2][32cp][512][128] (sliceH=32)
    conv3x3_mma<32, 0, 0, 0><<<dim3(2, 64, 4), 256, SM_FULL>>>(
        B, Wp + o3, A, 512, 128, 32, 2);

    // conv4 (+pool2 fused): A -> B fp16 [2][32cp][256][64]
    conv3x3_mma<64, 0, 1, 0><<<dim3(2, 64, 4), 256, SM_FULL>>>(
        A, Wp + o4, B, 512, 128, 32, 2);

    // conv5: B -> A fp16 [2][64cp][256][64] (1x3 middle row)
    conv3x3_mma<64, 1, 0, 0><<<dim3(1, 32, 8), 256, SM_ONE>>>(
        B, Wp + o5, A, 256, 64, 1, 4);

    // conv6: A -> out fp32 NCHW [2,128,256,64] (final)
    conv3x3_mma<128, 1, 0, 1><<<dim3(1, 32, 8), 256, SM_ONE>>>(
        A, Wp + o6, d_out, 256, 64, 1, 4);
}

// round 14
// speedup vs baseline: 2.2142x; 1.0150x over previous
#include <cuda_runtime.h>
#include <cuda_fp16.h>

// ---------------------------------------------------------------------------
// FrameLevelPartFeatureExtractor — FP16 tensor-core (mma.sync m16n8k16) conv
// pipeline. Intermediates fp16 cpair-interleaved [N][C/2][H][W][2].
// R14: weights staged ONCE (resident smem) for all MMA layers.
//   conv2/3/4: M=32 warp tile, 2-stage A pipeline, 3 blocks/SM (50% occ).
//   conv5/6 (ONEROW): M=64 warp tile, 3-stage A pipeline, 2 blocks/SM.
// conv2/conv4 fuse 2x2 maxpool. conv1 packed-f32x2 + folded weight pack.
// Final conv6 writes fp32 NCHW.
// ---------------------------------------------------------------------------

typedef unsigned int uint;
typedef unsigned long long u64;

__device__ __align__(16) uint g_bufA[8388608];
__device__ __align__(16) uint g_bufB[8388608];
__device__ __align__(16) uint g_bufW[69120];   // packed fp16 weights, w2..w6

__device__ __forceinline__ float dlrelu(float v) {
    return v > 0.0f ? v : 0.01f * (0.01f * v);
}
__device__ __forceinline__ uint pack_h2(float lo, float hi) {
    uint r; asm("cvt.rn.f16x2.f32 %0, %1, %2;" : "=r"(r) : "f"(hi), "f"(lo));
    return r;
}
__device__ __forceinline__ uint max_h2(uint a, uint b) {
    uint r; asm("max.f16x2 %0, %1, %2;" : "=r"(r) : "r"(a), "r"(b));
    return r;
}
__device__ __forceinline__ void cp16(unsigned dst, const void* src, int sz) {
    asm volatile("cp.async.cg.shared.global [%0], [%1], 16, %2;\n"
                 :: "r"(dst), "l"(src), "r"(sz));
}
__device__ __forceinline__ void cp4(unsigned dst, const void* src, int sz) {
    asm volatile("cp.async.ca.shared.global [%0], [%1], 4, %2;\n"
                 :: "r"(dst), "l"(src), "r"(sz));
}
__device__ __forceinline__ void cp_commit() {
    asm volatile("cp.async.commit_group;\n" ::);
}
__device__ __forceinline__ void mma_f16(float* c, uint a0, uint a1, uint a2,
                                        uint a3, uint b0, uint b1) {
    asm volatile(
        "mma.sync.aligned.m16n8k16.row.col.f32.f16.f16.f32 "
        "{%0,%1,%2,%3}, {%4,%5,%6,%7}, {%8,%9}, {%0,%1,%2,%3};"
        : "+f"(c[0]), "+f"(c[1]), "+f"(c[2]), "+f"(c[3])
        : "r"(a0), "r"(a1), "r"(a2), "r"(a3), "r"(b0), "r"(b1));
}
__device__ __forceinline__ u64 dup_f(float v) {
    u64 r; asm("mov.b64 %0, {%1, %1};" : "=l"(r) : "f"(v)); return r;
}
__device__ __forceinline__ void ffma2(u64& d, u64 a, u64 b) {
    asm("fma.rn.f32x2 %0, %1, %2, %0;" : "+l"(d) : "l"(a), "l"(b));
}
__device__ __forceinline__ float2 unpk(u64 a) {
    float2 f; asm("mov.b64 {%0, %1}, %2;" : "=f"(f.x), "=f"(f.y) : "l"(a));
    return f;
}

// ---------------------------------------------------------------------------
// conv1: 5x5, Cin=1, Cout=32, packed f32x2 FMA; fp16 cpair-interleaved out.
// First 270 blocks also pack the fp16 weights for layers 2..6 (69120 words).
// ---------------------------------------------------------------------------
__global__ __launch_bounds__(256, 2)
void conv5x5_c1(const float* __restrict__ in, const float* __restrict__ wgt,
                uint* __restrict__ out,
                const float* __restrict__ w2, const float* __restrict__ w3,
                const float* __restrict__ w4, const float* __restrict__ w5,
                const float* __restrict__ w6, uint* __restrict__ pk)
{
    const int H = 1024, W = 256, SL = 512, TH = 4, TW = 64;
    const int n  = blockIdx.z;
    const int h0 = blockIdx.y * TH;
    const int w0 = blockIdx.x * TW;
    const int tid = threadIdx.x;
    const int op0 = (tid & 3) * 4;
    const int lw  = ((tid >> 2) & 15) * 4;
    const int hh  = tid >> 6;

    __shared__ float si[TH + 4][TW + 4];
    __shared__ float2 swp[16][25];

    for (int i = tid; i < 32 * 25; i += 256) {
        int o = i / 25, t = i % 25;
        float v = wgt[i];
        if (o & 1) swp[o >> 1][t].y = v; else swp[o >> 1][t].x = v;
    }

    const int ss = (h0 / SL) * SL, se = ss + SL;
    for (int i = tid; i < (TH + 4) * (TW + 4); i += 256) {
        int r = i / (TW + 4), c = i % (TW + 4);
        int g = h0 - 2 + r, gc = w0 - 2 + c;
        float v = 0.0f;
        if (g >= ss && g < se && gc >= 0 && gc < W)
            v = in[(n * H + g) * W + gc];
        si[r][c] = v;
    }
    __syncthreads();

    u64 dup[5][8];
#pragma unroll
    for (int r = 0; r < 5; r++)
#pragma unroll
        for (int c = 0; c < 8; c++)
            dup[r][c] = dup_f(si[hh + r][lw + c]);

    u64 acc[4][4];
#pragma unroll
    for (int p = 0; p < 4; p++)
#pragma unroll
        for (int x = 0; x < 4; x++) acc[p][x] = 0ULL;

#pragma unroll
    for (int p = 0; p < 4; p++) {
        const u64* wp = reinterpret_cast<const u64*>(&swp[op0 + p][0]);
#pragma unroll
        for (int r = 0; r < 5; r++)
#pragma unroll
            for (int kc = 0; kc < 5; kc++) {
                u64 wv = wp[r * 5 + kc];
#pragma unroll
                for (int x = 0; x < 4; x++)
                    ffma2(acc[p][x], dup[r][kc + x], wv);
            }
    }

#pragma unroll
    for (int p = 0; p < 4; p++) {
        uint4 st;
        uint* sv = &st.x;
#pragma unroll
        for (int x = 0; x < 4; x++) {
            float2 f = unpk(acc[p][x]);
            sv[x] = pack_h2(dlrelu(f.x), dlrelu(f.y));
        }
        int ocp = (tid & 3) * 4 + p;
        uint* op = &out[(((size_t)n * 16 + ocp) * H + h0 + hh) * W + w0 + lw];
        *reinterpret_cast<uint4*>(op) = st;
    }

    // ---- folded weight pack ----
    {
        int bid = (blockIdx.z * gridDim.y + blockIdx.y) * gridDim.x + blockIdx.x;
        if (bid < 270) {
            int idx = bid * 256 + tid;
            const float* w; int CIN, NCH, TAPS_, local;
            if (idx < 4608)       { w = w2; CIN = 32;  NCH = 2; TAPS_ = 9; local = idx; }
            else if (idx < 13824) { w = w3; CIN = 32;  NCH = 2; TAPS_ = 9; local = idx - 4608; }
            else if (idx < 32256) { w = w4; CIN = 64;  NCH = 4; TAPS_ = 9; local = idx - 13824; }
            else if (idx < 44544) { w = w5; CIN = 64;  NCH = 4; TAPS_ = 3; local = idx - 32256; }
            else                  { w = w6; CIN = 128; NCH = 8; TAPS_ = 3; local = idx - 44544; }
            int j    = local & 1;
            int r1   = local >> 1;
            int lane = r1 & 31;
            int r2   = r1 >> 5;
            int nn   = r2 & 3;
            int r3   = r2 >> 2;
            int tap  = r3 % TAPS_;
            int r4   = r3 / TAPS_;
            int t    = r4 % NCH;
            int ocg  = r4 / NCH;
            int oc   = ocg * 32 + nn * 8 + (lane >> 2);
            int cin  = t * 16 + 2 * ((lane & 3) + 4 * j);
            int tapIdx = (TAPS_ == 3) ? (tap + 3) : tap;
            float v0 = w[(oc * CIN + cin) * 9 + tapIdx];
            float v1 = w[(oc * CIN + cin + 1) * 9 + tapIdx];
            pk[idx] = pack_h2(v0, v1);
        }
    }
}

// ---------------------------------------------------------------------------
// Non-ONEROW 3x3 conv (conv2/3/4): M=32 warp tile, 2-stage A pipeline,
// resident weights, 3 blocks/SM. Block tile 8h x 32w x 32oc; warp = one
// h-row, M=32 (2 m-subtiles) x N=32. K-chunk = 16 cin.
// POOL: fused 2x2 maxpool epilogue (stash aliases dead arena).
// ---------------------------------------------------------------------------
template <int CIN, int POOL>
__global__ __launch_bounds__(256, 3)
void conv3x3_s2(const uint* __restrict__ in, const uint* __restrict__ pk,
                void* __restrict__ outv, int H, int W, int sliceH, int OCG)
{
    constexpr int TH    = 8;
    constexpr int ROWS  = TH + 2;
    constexpr int PLANE = 424;                  // >=ROWS*40, ==8 mod 32, /4
    constexpr int SI_W  = 8 * PLANE;            // 3392 words
    constexpr int CHUNK_W = 9 * 256;            // 2304 words per cin-chunk
    constexpr int NCH   = CIN / 16;
    constexpr int W_TOT = NCH * CHUNK_W;
    constexpr int NROWOPS = 8 * ROWS * 10;      // 9 cp16 + 1 cp4 per row
    constexpr int NI    = (NROWOPS + 255) / 256;
    constexpr int NWT   = NCH * 9 * 64;         // resident-weight cp16 ops
    constexpr int NW    = (NWT + 255) / 256;
    constexpr int ARENA = 2 * SI_W + W_TOT;

    static_assert(!POOL || ARENA >= TH * 32 * 18, "pool stash fits");
    static_assert(NCH >= 2, "pipeline needs >= 2 chunks");

    extern __shared__ __align__(16) uint arena[];
    uint* si_p = arena;
    uint* sw_p = arena + 2 * SI_W;
    uint* sO   = arena;

    const int z    = blockIdx.z;
    const int ocg  = z % OCG;
    const int n    = z / OCG;
    const int h0   = blockIdx.y * TH;
    const int w0   = blockIdx.x * 32;
    const int tid  = threadIdx.x;
    const int lane = tid & 31;
    const int wid  = tid >> 5;
    const int g2 = lane >> 2;
    const int g4 = lane & 3;

    const int ss = (h0 / sliceH) * sliceH;
    const int se = ss + sliceH;

    const int C2in = CIN / 2;
    const uint* base = in + (size_t)n * C2in * H * W;
    const uint* pk0  = pk + (size_t)(ocg * NCH) * CHUNK_W;

    // ---- hoisted input staging descriptors ----
    int di_dst[NI], di_off[NI];
#pragma unroll
    for (int k = 0; k < NI; k++) {
        int i = tid + k * 256;
        int dst = -1, off = -1;
        if (i < NROWOPS) {
            int rowid = i / 10, sub = i - rowid * 10;
            int c = rowid / ROWS, r = rowid - c * ROWS;
            int g = h0 - 1 + r;
            bool rowok = (g >= ss && g < se);
            int word = c * PLANE + r * 40 + sub * 4;
            if (sub < 9) {
                int gc = w0 - 4 + sub * 4;
                dst = (word * 4) | 1;
                off = (rowok && gc >= 0) ? ((c * H + g) * W + gc) : -1;
            } else {
                int gc = w0 + 32;
                dst = word * 4;
                off = (rowok && gc < W) ? ((c * H + g) * W + gc) : -1;
            }
        }
        di_dst[k] = dst; di_off[k] = off;
    }

    unsigned si_s = (unsigned)__cvta_generic_to_shared(si_p);
    unsigned sw_s = (unsigned)__cvta_generic_to_shared(sw_p);

    auto stageA = [&](int t, int buf) {
        const uint* cb = base + (size_t)t * 8 * H * W;
        unsigned sd = si_s + (unsigned)buf * (SI_W * 4);
#pragma unroll
        for (int k = 0; k < NI; k++) {
            int d = di_dst[k];
            if (d >= 0) {
                int off = di_off[k];
                if (d & 1)
                    cp16(sd + (unsigned)(d ^ 1),
                         off >= 0 ? (const void*)(cb + off) : (const void*)cb,
                         off >= 0 ? 16 : 0);
                else
                    cp4(sd + (unsigned)d,
                        off >= 0 ? (const void*)(cb + off) : (const void*)cb,
                        off >= 0 ? 4 : 0);
            }
        }
    };

    // prologue: all weights + chunk 0, one group
#pragma unroll
    for (int k = 0; k < NW; k++) {
        int i = tid + k * 256;
        if (NWT % 256 == 0 || i < NWT)
            cp16(sw_s + (unsigned)i * 16, pk0 + i * 4, 16);
    }
    stageA(0, 0);
    cp_commit();

    float acc[2][4][4];
#pragma unroll
    for (int m = 0; m < 2; m++)
#pragma unroll
        for (int nn = 0; nn < 4; nn++)
#pragma unroll
            for (int x = 0; x < 4; x++) acc[m][nn][x] = 0.0f;

    const int abase = g4 * PLANE + wid * 40 + g2 + 3;
    const int a2off = 4 * PLANE;

    for (int t = 0; t < NCH; t++) {
        asm volatile("cp.async.wait_group 0;\n" ::);
        __syncthreads();
        if (t + 1 < NCH) { stageA(t + 1, (t + 1) & 1); cp_commit(); }

        const uint* sif = si_p + (t & 1) * SI_W;
        const uint* sbf = sw_p + t * CHUNK_W;
#pragma unroll
        for (int r = 0; r < 3; r++) {
#pragma unroll
            for (int q = 0; q < 3; q++) {
                const int tap = r * 3 + q;
                uint b[4][2];
#pragma unroll
                for (int nn = 0; nn < 4; nn++) {
                    uint2 v = *reinterpret_cast<const uint2*>(
                        sbf + ((tap * 4 + nn) * 32 + lane) * 2);
                    b[nn][0] = v.x;
                    b[nn][1] = v.y;
                }
#pragma unroll
                for (int m = 0; m < 2; m++) {
                    int ai = abase + r * 40 + q + m * 16;
                    uint a0 = sif[ai];
                    uint a1 = sif[ai + 8];
                    uint a2 = sif[ai + a2off];
                    uint a3 = sif[ai + a2off + 8];
#pragma unroll
                    for (int nn = 0; nn < 4; nn++)
                        mma_f16(acc[m][nn], a0, a1, a2, a3,
                                b[nn][0], b[nn][1]);
                }
            }
        }
    }

    // ---- epilogue ----
    if (POOL) {
        __syncthreads();
#pragma unroll
        for (int m = 0; m < 2; m++)
#pragma unroll
            for (int nn = 0; nn < 4; nn++) {
                int ocp = nn * 4 + g4;
                int wl  = m * 16 + g2;
                sO[wid * (32 * 18) + wl * 18 + ocp] =
                    pack_h2(dlrelu(acc[m][nn][0]), dlrelu(acc[m][nn][1]));
                sO[wid * (32 * 18) + (wl + 8) * 18 + ocp] =
                    pack_h2(dlrelu(acc[m][nn][2]), dlrelu(acc[m][nn][3]));
            }
        __syncthreads();
        uint* out = (uint*)outv;
        const int C2out = OCG * 16;
        const int H2 = H >> 1, W2 = W >> 1;
        const int pw = tid & 15, ph = (tid >> 4) & 3, ob = tid >> 6;
#pragma unroll
        for (int k = 0; k < 4; k++) {
            int ocp = ob * 4 + k;
            const uint* s0 = sO + (2 * ph) * (32 * 18) + (2 * pw) * 18 + ocp;
            uint v = max_h2(max_h2(s0[0], s0[18]),
                            max_h2(s0[32 * 18], s0[32 * 18 + 18]));
            out[((size_t)(n * C2out + ocg * 16 + ocp) * H2 + (h0 >> 1) + ph) * W2
                + (w0 >> 1) + pw] = v;
        }
    } else {
        uint* out = (uint*)outv;
        const int C2out = OCG * 16;
        const int h = h0 + wid;
#pragma unroll
        for (int m = 0; m < 2; m++) {
#pragma unroll
            for (int nn = 0; nn < 4; nn++) {
                int ocp = ocg * 16 + nn * 4 + g4;
                int wv  = w0 + m * 16 + g2;
                uint* p = out + ((size_t)(n * C2out + ocp) * H + h) * W + wv;
                p[0] = pack_h2(dlrelu(acc[m][nn][0]), dlrelu(acc[m][nn][1]));
                p[8] = pack_h2(dlrelu(acc[m][nn][2]), dlrelu(acc[m][nn][3]));
            }
        }
    }
}

// ---------------------------------------------------------------------------
// ONEROW 1x3 conv (conv5/6): M=64 warp tile, 3-stage A pipeline, resident
// weights. Block tile 8h x 64w x 32oc; warp = one h row, M=64 x N=32.
// B fragments preloaded across all 3 taps. FINAL: fp32 NCHW output.
// ---------------------------------------------------------------------------
template <int CIN, int FINAL>
__global__ __launch_bounds__(256, 2)
void conv1x3_s3(const uint* __restrict__ in, const uint* __restrict__ pk,
                void* __restrict__ outv, int H, int W, int OCG)
{
    constexpr int TH    = 8;
    constexpr int ROWS  = TH;
    constexpr int PLANE = 584;                  // >=ROWS*72, ==8 mod 32, /4
    constexpr int SI_W  = 8 * PLANE;            // 4672 words
    constexpr int CHUNK_W = 3 * 256;            // 768 words per cin-chunk
    constexpr int NCH   = CIN / 16;
    constexpr int W_TOT = NCH * CHUNK_W;
    constexpr int NROWOPS = 8 * ROWS * 18;      // 18 cp16 per row
    constexpr int NI    = (NROWOPS + 255) / 256;
    constexpr int NWT   = NCH * 3 * 64;
    constexpr int NW    = (NWT + 255) / 256;

    static_assert(NCH >= 2, "pipeline needs >= 2 chunks");

    extern __shared__ __align__(16) uint arena[];
    uint* si_p = arena;
    uint* sw_p = arena + 3 * SI_W;

    const int z    = blockIdx.z;
    const int ocg  = z % OCG;
    const int n    = z / OCG;
    const int h0   = blockIdx.y * TH;
    const int w0   = blockIdx.x * 64;
    const int tid  = threadIdx.x;
    const int lane = tid & 31;
    const int wid  = tid >> 5;
    const int g2 = lane >> 2;
    const int g4 = lane & 3;

    const int C2in = CIN / 2;
    const uint* base = in + (size_t)n * C2in * H * W;
    const uint* pk0  = pk + (size_t)(ocg * NCH) * CHUNK_W;

    int di_dst[NI], di_off[NI];
#pragma unroll
    for (int k = 0; k < NI; k++) {
        int i = tid + k * 256;
        int dst = -1, off = -1;
        if (i < NROWOPS) {
            int rowid = i / 18, sub = i - rowid * 18;
            int c = rowid / ROWS, r = rowid - c * ROWS;
            int g = h0 + r;
            int gc = w0 - 4 + sub * 4;
            dst = (c * PLANE + r * 72 + sub * 4) * 4;
            off = (gc >= 0 && gc < W) ? ((c * H + g) * W + gc) : -1;
        }
        di_dst[k] = dst; di_off[k] = off;
    }

    unsigned si_s = (unsigned)__cvta_generic_to_shared(si_p);
    unsigned sw_s = (unsigned)__cvta_generic_to_shared(sw_p);

    auto stageA = [&](int t, int buf) {
        const uint* cb = base + (size_t)t * 8 * H * W;
        unsigned sd = si_s + (unsigned)buf * (SI_W * 4);
#pragma unroll
        for (int k = 0; k < NI; k++) {
            int d = di_dst[k];
            if (d >= 0) {
                int off = di_off[k];
                cp16(sd + (unsigned)d,
                     off >= 0 ? (const void*)(cb + off) : (const void*)cb,
                     off >= 0 ? 16 : 0);
            }
        }
    };

    // prologue: weights + chunk 0 in group, then chunk 1
#pragma unroll
    for (int k = 0; k < NW; k++) {
        int i = tid + k * 256;
        if (NWT % 256 == 0 || i < NWT)
            cp16(sw_s + (unsigned)i * 16, pk0 + i * 4, 16);
    }
    stageA(0, 0);
    cp_commit();
    stageA(1, 1);
    cp_commit();

    float acc[4][4][4];
#pragma unroll
    for (int m = 0; m < 4; m++)
#pragma unroll
        for (int nn = 0; nn < 4; nn++)
#pragma unroll
            for (int x = 0; x < 4; x++) acc[m][nn][x] = 0.0f;

    const int abase = g4 * PLANE + wid * 72 + g2 + 3;
    const int a2off = 4 * PLANE;

    for (int t = 0; t < NCH; t++) {
        if (t + 1 < NCH) asm volatile("cp.async.wait_group 1;\n" ::);
        else             asm volatile("cp.async.wait_group 0;\n" ::);
        __syncthreads();
        if (t + 2 < NCH) { stageA(t + 2, (t + 2) % 3); cp_commit(); }

        const uint* sif = si_p + (t % 3) * SI_W;
        const uint* sbf = sw_p + t * CHUNK_W;

        uint ball[3][4][2];
#pragma unroll
        for (int q = 0; q < 3; q++)
#pragma unroll
            for (int nn = 0; nn < 4; nn++) {
                uint2 v = *reinterpret_cast<const uint2*>(
                    sbf + ((q * 4 + nn) * 32 + lane) * 2);
                ball[q][nn][0] = v.x;
                ball[q][nn][1] = v.y;
            }
#pragma unroll
        for (int q = 0; q < 3; q++) {
#pragma unroll
            for (int m = 0; m < 4; m++) {
                int ai = abase + q + m * 16;
                uint a0 = sif[ai];
                uint a1 = sif[ai + 8];
                uint a2 = sif[ai + a2off];
                uint a3 = sif[ai + a2off + 8];
#pragma unroll
                for (int nn = 0; nn < 4; nn++)
                    mma_f16(acc[m][nn], a0, a1, a2, a3,
                            ball[q][nn][0], ball[q][nn][1]);
            }
        }
    }

    // ---- epilogue ----
    if (FINAL) {
        float* out = (float*)outv;
        const int Cout = OCG * 32;
        const int h = h0 + wid;
#pragma unroll
        for (int m = 0; m < 4; m++) {
#pragma unroll
            for (int nn = 0; nn < 4; nn++) {
                int oc = ocg * 32 + nn * 8 + 2 * g4;
                int wv = w0 + m * 16 + g2;
                float* p0 = out + ((size_t)(n * Cout + oc) * H + h) * W + wv;
                float* p1 = p0 + (size_t)H * W;
                p0[0] = dlrelu(acc[m][nn][0]);
                p1[0] = dlrelu(acc[m][nn][1]);
                p0[8] = dlrelu(acc[m][nn][2]);
                p1[8] = dlrelu(acc[m][nn][3]);
            }
        }
    } else {
        uint* out = (uint*)outv;
        const int C2out = OCG * 16;
        const int h = h0 + wid;
#pragma unroll
        for (int m = 0; m < 4; m++) {
#pragma unroll
            for (int nn = 0; nn < 4; nn++) {
                int ocp = ocg * 16 + nn * 4 + g4;
                int wv  = w0 + m * 16 + g2;
                uint* p = out + ((size_t)(n * C2out + ocp) * H + h) * W + wv;
                p[0] = pack_h2(dlrelu(acc[m][nn][0]), dlrelu(acc[m][nn][1]));
                p[8] = pack_h2(dlrelu(acc[m][nn][2]), dlrelu(acc[m][nn][3]));
            }
        }
    }
}

// ---------------------------------------------------------------------------
extern "C" void kernel_launch(void* const* d_in, const int* in_sizes, int n_in,
                              void* d_out, int out_size)
{
    const float* x  = (const float*)d_in[0];
    const float* w1 = (const float*)d_in[1];
    const float* w2 = (const float*)d_in[2];
    const float* w3 = (const float*)d_in[3];
    const float* w4 = (const float*)d_in[4];
    const float* w5 = (const float*)d_in[5];
    const float* w6 = (const float*)d_in[6];

    uint *A, *B, *Wp;
    cudaGetSymbolAddress((void**)&A, g_bufA);
    cudaGetSymbolAddress((void**)&B, g_bufB);
    cudaGetSymbolAddress((void**)&Wp, g_bufW);

    const int o2 = 0, o3 = 4608, o4 = 13824, o5 = 32256, o6 = 44544;

    // Dynamic smem sizes (bytes)
    const int SM_C2 = (2 * 3392 + 2 * 2304) * 4;   // 45568 (CIN=32)
    const int SM_C4 = (2 * 3392 + 4 * 2304) * 4;   // 64000 (CIN=64)
    const int SM_O5 = (3 * 4672 + 4 * 768) * 4;    // 68352 (CIN=64 ONEROW)
    const int SM_O6 = (3 * 4672 + 8 * 768) * 4;    // 80640 (CIN=128 ONEROW)

    cudaFuncSetAttribute(conv3x3_s2<32, 1>,
                         cudaFuncAttributeMaxDynamicSharedMemorySize, SM_C2);
    cudaFuncSetAttribute(conv3x3_s2<32, 0>,
                         cudaFuncAttributeMaxDynamicSharedMemorySize, SM_C2);
    cudaFuncSetAttribute(conv3x3_s2<64, 1>,
                         cudaFuncAttributeMaxDynamicSharedMemorySize, SM_C4);
    cudaFuncSetAttribute(conv1x3_s3<64, 0>,
                         cudaFuncAttributeMaxDynamicSharedMemorySize, SM_O5);
    cudaFuncSetAttribute(conv1x3_s3<128, 1>,
                         cudaFuncAttributeMaxDynamicSharedMemorySize, SM_O6);

    // conv1 (+folded weight pack): x -> A fp16 [2][16cp][1024][256]
    conv5x5_c1<<<dim3(4, 256, 2), 256>>>(x, w1, A, w2, w3, w4, w5, w6, Wp);

    // conv2 (+pool1 fused): A -> B fp16 [2][16cp][512][128]
    conv3x3_s2<32, 1><<<dim3(8, 128, 2), 256, SM_C2>>>(
        A, Wp + o2, B, 1024, 256, 512, 1);

    // conv3: B -> A fp16 [2][32cp][512][128] (sliceH=32)
    conv3x3_s2<32, 0><<<dim3(4, 64, 4), 256, SM_C2>>>(
        B, Wp + o3, A, 512, 128, 32, 2);

    // conv4 (+pool2 fused): A -> B fp16 [2][32cp][256][64]
    conv3x3_s2<64, 1><<<dim3(4, 64, 4), 256, SM_C4>>>(
        A, Wp + o4, B, 512, 128, 32, 2);

    // conv5: B -> A fp16 [2][64cp][256][64] (1x3 middle row)
    conv1x3_s3<64, 0><<<dim3(1, 32, 8), 256, SM_O5>>>(
        B, Wp + o5, A, 256, 64, 4);

    // conv6: A -> out fp32 NCHW [2,128,256,64] (final)
    conv1x3_s3<128, 1><<<dim3(1, 32, 8), 256, SM_O6>>>(
        A, Wp + o6, d_out, 256, 64, 4);
}

// round 16
// speedup vs baseline: 2.3851x; 1.0772x over previous
#include <cuda_runtime.h>
#include <cuda_fp16.h>

// ---------------------------------------------------------------------------
// FrameLevelPartFeatureExtractor — FP16 tensor-core (mma.sync m16n8k16) conv
// pipeline. Intermediates fp16 cpair-interleaved [N][C/2][H][W][2].
// R16: conv1 ALSO on tensor cores (im2col, K=25->32). tcgen05 is unavailable
// (harness compiles .target sm_100, no 'a' features).
//   conv1: im2col MMA, 8h x 64w x 32oc + folded weight pack (blocks 0-269)
//   conv2/3/4: mma.sync M=32 tile, 2-stage A pipeline, resident weights,
//              3 blocks/SM; conv2/conv4 fuse 2x2 maxpool
//   conv5/6 (ONEROW 1x3): M=64 tile, 3-stage pipeline, resident weights
// Final conv6 writes fp32 NCHW.
// ---------------------------------------------------------------------------

typedef unsigned int uint;
typedef unsigned long long u64;

__device__ __align__(16) uint g_bufA[8388608];
__device__ __align__(16) uint g_bufB[8388608];
__device__ __align__(16) uint g_bufW[69120];   // packed fp16 weights, w2..w6

__device__ __forceinline__ float dlrelu(float v) {
    return v > 0.0f ? v : 0.01f * (0.01f * v);
}
__device__ __forceinline__ uint pack_h2(float lo, float hi) {
    uint r; asm("cvt.rn.f16x2.f32 %0, %1, %2;" : "=r"(r) : "f"(hi), "f"(lo));
    return r;
}
__device__ __forceinline__ uint max_h2(uint a, uint b) {
    uint r; asm("max.f16x2 %0, %1, %2;" : "=r"(r) : "r"(a), "r"(b));
    return r;
}
__device__ __forceinline__ void cp16(unsigned dst, const void* src, int sz) {
    asm volatile("cp.async.cg.shared.global [%0], [%1], 16, %2;\n"
                 :: "r"(dst), "l"(src), "r"(sz));
}
__device__ __forceinline__ void cp4(unsigned dst, const void* src, int sz) {
    asm volatile("cp.async.ca.shared.global [%0], [%1], 4, %2;\n"
                 :: "r"(dst), "l"(src), "r"(sz));
}
__device__ __forceinline__ void cp_commit() {
    asm volatile("cp.async.commit_group;\n" ::);
}
__device__ __forceinline__ void mma_f16(float* c, uint a0, uint a1, uint a2,
                                        uint a3, uint b0, uint b1) {
    asm volatile(
        "mma.sync.aligned.m16n8k16.row.col.f32.f16.f16.f32 "
        "{%0,%1,%2,%3}, {%4,%5,%6,%7}, {%8,%9}, {%0,%1,%2,%3};"
        : "+f"(c[0]), "+f"(c[1]), "+f"(c[2]), "+f"(c[3])
        : "r"(a0), "r"(a1), "r"(a2), "r"(a3), "r"(b0), "r"(b1));
}

// ---------------------------------------------------------------------------
// conv1 via im2col MMA: 5x5, Cin=1, Cout=32, K = 25 taps padded to 32.
// Block 8h x 64w x 32oc; warp = one h row, M=64 (4 m-subtiles) x N=32.
// A im2col smem [8h][64w][32k] fp16 (pixel stride 20 words, conflict-free
// fragment reads). B packed in-block to fragment uint2 layout.
// First 270 blocks also pack the fp16 weights for layers 2..6.
// ---------------------------------------------------------------------------
__global__ __launch_bounds__(256, 2)
void conv1_mma(const float* __restrict__ in, const float* __restrict__ w1,
               uint* __restrict__ out,
               const float* __restrict__ w2, const float* __restrict__ w3,
               const float* __restrict__ w4, const float* __restrict__ w5,
               const float* __restrict__ w6, uint* __restrict__ pk)
{
    extern __shared__ __align__(16) uint arena1[];
    float* sfl = (float*)arena1;            //   832 words: fp32 tile [12][68]
    uint*  A_s = arena1 + 832;              // 10240 words: im2col A
    uint*  B_s = arena1 + 832 + 10240;      //   512 words: packed B

    const int H = 1024, W = 256;
    const int n  = blockIdx.z;
    const int h0 = blockIdx.y * 8;
    const int w0 = blockIdx.x * 64;
    const int tid  = threadIdx.x;
    const int lane = tid & 31;
    const int wid  = tid >> 5;
    const int g2 = lane >> 2, g4 = lane & 3;

    // ---- stage fp32 input tile [12][68] with slice/border guards ----
    const int ss = (h0 >> 9) << 9;          // sliceH = 512
    for (int i = tid; i < 816; i += 256) {
        int r = i / 68, c = i - r * 68;
        int g = h0 - 2 + r, gc = w0 - 2 + c;
        float v = 0.0f;
        if (g >= ss && g < ss + 512 && gc >= 0 && gc < W)
            v = in[((size_t)n * H + g) * W + gc];
        sfl[r * 68 + c] = v;
    }

    // ---- pack B (one uint2 per thread): [kc][nn][lane] fragment layout ----
    {
        int kc = tid >> 7, nn = (tid >> 5) & 3, ln = tid & 31;
        int oc = nn * 8 + (ln >> 2);
        int kb = kc * 16 + 2 * (ln & 3);
        float f0 = (kb     < 25) ? w1[oc * 25 + kb]     : 0.0f;
        float f1 = (kb + 1 < 25) ? w1[oc * 25 + kb + 1] : 0.0f;
        float f2 = (kb + 8 < 25) ? w1[oc * 25 + kb + 8] : 0.0f;
        float f3 = (kb + 9 < 25) ? w1[oc * 25 + kb + 9] : 0.0f;
        B_s[((kc * 4 + nn) * 32 + ln) * 2]     = pack_h2(f0, f1);
        B_s[((kc * 4 + nn) * 32 + ln) * 2 + 1] = pack_h2(f2, f3);
    }
    __syncthreads();

    // ---- build im2col A: word (h,w,j) = half2 of taps (2j, 2j+1) ----
    for (int it = 0; it < 32; it++) {
        int i = tid + it * 256;             // 0..8191
        int j = i & 15;
        int w = (i >> 4) & 63;
        int h = i >> 10;
        int k0 = 2 * j, k1 = k0 + 1;
        float v0 = 0.0f, v1 = 0.0f;
        if (k0 < 25) v0 = sfl[(h + k0 / 5) * 68 + (w + k0 % 5)];
        if (k1 < 25) v1 = sfl[(h + k1 / 5) * 68 + (w + k1 % 5)];
        A_s[(h * 64 + w) * 20 + j] = pack_h2(v0, v1);
    }
    __syncthreads();

    // ---- 32 mmas per warp (2 kc x 4 m x 4 nn) ----
    float acc[4][4][4];
#pragma unroll
    for (int m = 0; m < 4; m++)
#pragma unroll
        for (int nn = 0; nn < 4; nn++)
#pragma unroll
            for (int x = 0; x < 4; x++) acc[m][nn][x] = 0.0f;

    const int abase = (wid * 64 + g2) * 20 + g4;
#pragma unroll
    for (int kc = 0; kc < 2; kc++) {
        uint b[4][2];
#pragma unroll
        for (int nn = 0; nn < 4; nn++) {
            uint2 v = reinterpret_cast<const uint2*>(B_s)[(kc * 4 + nn) * 32 + lane];
            b[nn][0] = v.x;
            b[nn][1] = v.y;
        }
#pragma unroll
        for (int m = 0; m < 4; m++) {
            int ai = abase + m * 320 + kc * 8;     // m*16 pixels * 20 words
            uint a0 = A_s[ai];
            uint a1 = A_s[ai + 160];               // +8 pixels
            uint a2 = A_s[ai + 4];
            uint a3 = A_s[ai + 164];
#pragma unroll
            for (int nn = 0; nn < 4; nn++)
                mma_f16(acc[m][nn], a0, a1, a2, a3, b[nn][0], b[nn][1]);
        }
    }

    // ---- epilogue: dlrelu + cpair-interleaved fp16 write ----
    const int h = h0 + wid;
#pragma unroll
    for (int m = 0; m < 4; m++) {
#pragma unroll
        for (int nn = 0; nn < 4; nn++) {
            int ocp = nn * 4 + g4;
            int wv  = w0 + m * 16 + g2;
            uint* p = out + (((size_t)n * 16 + ocp) * H + h) * W + wv;
            p[0] = pack_h2(dlrelu(acc[m][nn][0]), dlrelu(acc[m][nn][1]));
            p[8] = pack_h2(dlrelu(acc[m][nn][2]), dlrelu(acc[m][nn][3]));
        }
    }

    // ---- folded weight pack for layers 2..6 (blocks 0..269) ----
    {
        int bid = (blockIdx.z * gridDim.y + blockIdx.y) * gridDim.x + blockIdx.x;
        if (bid < 270) {
            int idx = bid * 256 + tid;
            const float* w; int CIN, NCH, TAPS_, local;
            if (idx < 4608)       { w = w2; CIN = 32;  NCH = 2; TAPS_ = 9; local = idx; }
            else if (idx < 13824) { w = w3; CIN = 32;  NCH = 2; TAPS_ = 9; local = idx - 4608; }
            else if (idx < 32256) { w = w4; CIN = 64;  NCH = 4; TAPS_ = 9; local = idx - 13824; }
            else if (idx < 44544) { w = w5; CIN = 64;  NCH = 4; TAPS_ = 3; local = idx - 32256; }
            else                  { w = w6; CIN = 128; NCH = 8; TAPS_ = 3; local = idx - 44544; }
            int j    = local & 1;
            int r1   = local >> 1;
            int ln   = r1 & 31;
            int r2   = r1 >> 5;
            int nn   = r2 & 3;
            int r3   = r2 >> 2;
            int tap  = r3 % TAPS_;
            int r4   = r3 / TAPS_;
            int t    = r4 % NCH;
            int ocg  = r4 / NCH;
            int oc   = ocg * 32 + nn * 8 + (ln >> 2);
            int cin  = t * 16 + 2 * ((ln & 3) + 4 * j);
            int tapIdx = (TAPS_ == 3) ? (tap + 3) : tap;
            float v0 = w[(oc * CIN + cin) * 9 + tapIdx];
            float v1 = w[(oc * CIN + cin + 1) * 9 + tapIdx];
            pk[idx] = pack_h2(v0, v1);
        }
    }
}

// ---------------------------------------------------------------------------
// Non-ONEROW 3x3 conv (conv2/3/4): M=32 warp tile, 2-stage A pipeline,
// resident weights, 3 blocks/SM. Block tile 8h x 32w x 32oc.
// POOL: fused 2x2 maxpool epilogue (stash aliases dead arena).
// ---------------------------------------------------------------------------
template <int CIN, int POOL>
__global__ __launch_bounds__(256, 3)
void conv3x3_s2(const uint* __restrict__ in, const uint* __restrict__ pk,
                void* __restrict__ outv, int H, int W, int sliceH, int OCG)
{
    constexpr int TH    = 8;
    constexpr int ROWS  = TH + 2;
    constexpr int PLANE = 424;
    constexpr int SI_W  = 8 * PLANE;
    constexpr int CHUNK_W = 9 * 256;
    constexpr int NCH   = CIN / 16;
    constexpr int NROWOPS = 8 * ROWS * 10;
    constexpr int NI    = (NROWOPS + 255) / 256;
    constexpr int NWT   = NCH * 9 * 64;
    constexpr int NW    = (NWT + 255) / 256;
    constexpr int ARENA = 2 * SI_W + NCH * CHUNK_W;

    static_assert(!POOL || ARENA >= TH * 32 * 18, "pool stash fits");
    static_assert(NCH >= 2, "pipeline needs >= 2 chunks");

    extern __shared__ __align__(16) uint arena[];
    uint* si_p = arena;
    uint* sw_p = arena + 2 * SI_W;
    uint* sO   = arena;

    const int z    = blockIdx.z;
    const int ocg  = z % OCG;
    const int n    = z / OCG;
    const int h0   = blockIdx.y * TH;
    const int w0   = blockIdx.x * 32;
    const int tid  = threadIdx.x;
    const int lane = tid & 31;
    const int wid  = tid >> 5;
    const int g2 = lane >> 2;
    const int g4 = lane & 3;

    const int ss = (h0 / sliceH) * sliceH;
    const int se = ss + sliceH;

    const int C2in = CIN / 2;
    const uint* base = in + (size_t)n * C2in * H * W;
    const uint* pk0  = pk + (size_t)(ocg * NCH) * CHUNK_W;

    int di_dst[NI], di_off[NI];
#pragma unroll
    for (int k = 0; k < NI; k++) {
        int i = tid + k * 256;
        int dst = -1, off = -1;
        if (i < NROWOPS) {
            int rowid = i / 10, sub = i - rowid * 10;
            int c = rowid / ROWS, r = rowid - c * ROWS;
            int g = h0 - 1 + r;
            bool rowok = (g >= ss && g < se);
            int word = c * PLANE + r * 40 + sub * 4;
            if (sub < 9) {
                int gc = w0 - 4 + sub * 4;
                dst = (word * 4) | 1;
                off = (rowok && gc >= 0) ? ((c * H + g) * W + gc) : -1;
            } else {
                int gc = w0 + 32;
                dst = word * 4;
                off = (rowok && gc < W) ? ((c * H + g) * W + gc) : -1;
            }
        }
        di_dst[k] = dst; di_off[k] = off;
    }

    unsigned si_s = (unsigned)__cvta_generic_to_shared(si_p);
    unsigned sw_s = (unsigned)__cvta_generic_to_shared(sw_p);

    auto stageA = [&](int t, int buf) {
        const uint* cb = base + (size_t)t * 8 * H * W;
        unsigned sd = si_s + (unsigned)buf * (SI_W * 4);
#pragma unroll
        for (int k = 0; k < NI; k++) {
            int d = di_dst[k];
            if (d >= 0) {
                int off = di_off[k];
                if (d & 1)
                    cp16(sd + (unsigned)(d ^ 1),
                         off >= 0 ? (const void*)(cb + off) : (const void*)cb,
                         off >= 0 ? 16 : 0);
                else
                    cp4(sd + (unsigned)d,
                        off >= 0 ? (const void*)(cb + off) : (const void*)cb,
                        off >= 0 ? 4 : 0);
            }
        }
    };

#pragma unroll
    for (int k = 0; k < NW; k++) {
        int i = tid + k * 256;
        if (NWT % 256 == 0 || i < NWT)
            cp16(sw_s + (unsigned)i * 16, pk0 + i * 4, 16);
    }
    stageA(0, 0);
    cp_commit();

    float acc[2][4][4];
#pragma unroll
    for (int m = 0; m < 2; m++)
#pragma unroll
        for (int nn = 0; nn < 4; nn++)
#pragma unroll
            for (int x = 0; x < 4; x++) acc[m][nn][x] = 0.0f;

    const int abase = g4 * PLANE + wid * 40 + g2 + 3;
    const int a2off = 4 * PLANE;

    for (int t = 0; t < NCH; t++) {
        asm volatile("cp.async.wait_group 0;\n" ::);
        __syncthreads();
        if (t + 1 < NCH) { stageA(t + 1, (t + 1) & 1); cp_commit(); }

        const uint* sif = si_p + (t & 1) * SI_W;
        const uint* sbf = sw_p + t * CHUNK_W;
#pragma unroll
        for (int r = 0; r < 3; r++) {
#pragma unroll
            for (int q = 0; q < 3; q++) {
                const int tap = r * 3 + q;
                uint b[4][2];
#pragma unroll
                for (int nn = 0; nn < 4; nn++) {
                    uint2 v = *reinterpret_cast<const uint2*>(
                        sbf + ((tap * 4 + nn) * 32 + lane) * 2);
                    b[nn][0] = v.x;
                    b[nn][1] = v.y;
                }
#pragma unroll
                for (int m = 0; m < 2; m++) {
                    int ai = abase + r * 40 + q + m * 16;
                    uint a0 = sif[ai];
                    uint a1 = sif[ai + 8];
                    uint a2 = sif[ai + a2off];
                    uint a3 = sif[ai + a2off + 8];
#pragma unroll
                    for (int nn = 0; nn < 4; nn++)
                        mma_f16(acc[m][nn], a0, a1, a2, a3,
                                b[nn][0], b[nn][1]);
                }
            }
        }
    }

    if (POOL) {
        __syncthreads();
#pragma unroll
        for (int m = 0; m < 2; m++)
#pragma unroll
            for (int nn = 0; nn < 4; nn++) {
                int ocp = nn * 4 + g4;
                int wl  = m * 16 + g2;
                sO[wid * (32 * 18) + wl * 18 + ocp] =
                    pack_h2(dlrelu(acc[m][nn][0]), dlrelu(acc[m][nn][1]));
                sO[wid * (32 * 18) + (wl + 8) * 18 + ocp] =
                    pack_h2(dlrelu(acc[m][nn][2]), dlrelu(acc[m][nn][3]));
            }
        __syncthreads();
        uint* out = (uint*)outv;
        const int C2out = OCG * 16;
        const int H2 = H >> 1, W2 = W >> 1;
        const int pw = tid & 15, ph = (tid >> 4) & 3, ob = tid >> 6;
#pragma unroll
        for (int k = 0; k < 4; k++) {
            int ocp = ob * 4 + k;
            const uint* s0 = sO + (2 * ph) * (32 * 18) + (2 * pw) * 18 + ocp;
            uint v = max_h2(max_h2(s0[0], s0[18]),
                            max_h2(s0[32 * 18], s0[32 * 18 + 18]));
            out[((size_t)(n * C2out + ocg * 16 + ocp) * H2 + (h0 >> 1) + ph) * W2
                + (w0 >> 1) + pw] = v;
        }
    } else {
        uint* out = (uint*)outv;
        const int C2out = OCG * 16;
        const int h = h0 + wid;
#pragma unroll
        for (int m = 0; m < 2; m++) {
#pragma unroll
            for (int nn = 0; nn < 4; nn++) {
                int ocp = ocg * 16 + nn * 4 + g4;
                int wv  = w0 + m * 16 + g2;
                uint* p = out + ((size_t)(n * C2out + ocp) * H + h) * W + wv;
                p[0] = pack_h2(dlrelu(acc[m][nn][0]), dlrelu(acc[m][nn][1]));
                p[8] = pack_h2(dlrelu(acc[m][nn][2]), dlrelu(acc[m][nn][3]));
            }
        }
    }
}

// ---------------------------------------------------------------------------
// ONEROW 1x3 conv (conv5/6): M=64 warp tile, 3-stage A pipeline, resident
// weights. Block tile 8h x 64w x 32oc; warp = one h row, M=64 x N=32.
// B fragments preloaded across all 3 taps. FINAL: fp32 NCHW output.
// ---------------------------------------------------------------------------
template <int CIN, int FINAL>
__global__ __launch_bounds__(256, 2)
void conv1x3_s3(const uint* __restrict__ in, const uint* __restrict__ pk,
                void* __restrict__ outv, int H, int W, int OCG)
{
    constexpr int TH    = 8;
    constexpr int ROWS  = TH;
    constexpr int PLANE = 584;
    constexpr int SI_W  = 8 * PLANE;
    constexpr int CHUNK_W = 3 * 256;
    constexpr int NCH   = CIN / 16;
    constexpr int NROWOPS = 8 * ROWS * 18;
    constexpr int NI    = (NROWOPS + 255) / 256;
    constexpr int NWT   = NCH * 3 * 64;
    constexpr int NW    = (NWT + 255) / 256;

    static_assert(NCH >= 2, "pipeline needs >= 2 chunks");

    extern __shared__ __align__(16) uint arena[];
    uint* si_p = arena;
    uint* sw_p = arena + 3 * SI_W;

    const int z    = blockIdx.z;
    const int ocg  = z % OCG;
    const int n    = z / OCG;
    const int h0   = blockIdx.y * TH;
    const int w0   = blockIdx.x * 64;
    const int tid  = threadIdx.x;
    const int lane = tid & 31;
    const int wid  = tid >> 5;
    const int g2 = lane >> 2;
    const int g4 = lane & 3;

    const int C2in = CIN / 2;
    const uint* base = in + (size_t)n * C2in * H * W;
    const uint* pk0  = pk + (size_t)(ocg * NCH) * CHUNK_W;

    int di_dst[NI], di_off[NI];
#pragma unroll
    for (int k = 0; k < NI; k++) {
        int i = tid + k * 256;
        int dst = -1, off = -1;
        if (i < NROWOPS) {
            int rowid = i / 18, sub = i - rowid * 18;
            int c = rowid / ROWS, r = rowid - c * ROWS;
            int g = h0 + r;
            int gc = w0 - 4 + sub * 4;
            dst = (c * PLANE + r * 72 + sub * 4) * 4;
            off = (gc >= 0 && gc < W) ? ((c * H + g) * W + gc) : -1;
        }
        di_dst[k] = dst; di_off[k] = off;
    }

    unsigned si_s = (unsigned)__cvta_generic_to_shared(si_p);
    unsigned sw_s = (unsigned)__cvta_generic_to_shared(sw_p);

    auto stageA = [&](int t, int buf) {
        const uint* cb = base + (size_t)t * 8 * H * W;
        unsigned sd = si_s + (unsigned)buf * (SI_W * 4);
#pragma unroll
        for (int k = 0; k < NI; k++) {
            int d = di_dst[k];
            if (d >= 0) {
                int off = di_off[k];
                cp16(sd + (unsigned)d,
                     off >= 0 ? (const void*)(cb + off) : (const void*)cb,
                     off >= 0 ? 16 : 0);
            }
        }
    };

#pragma unroll
    for (int k = 0; k < NW; k++) {
        int i = tid + k * 256;
        if (NWT % 256 == 0 || i < NWT)
            cp16(sw_s + (unsigned)i * 16, pk0 + i * 4, 16);
    }
    stageA(0, 0);
    cp_commit();
    stageA(1, 1);
    cp_commit();

    float acc[4][4][4];
#pragma unroll
    for (int m = 0; m < 4; m++)
#pragma unroll
        for (int nn = 0; nn < 4; nn++)
#pragma unroll
            for (int x = 0; x < 4; x++) acc[m][nn][x] = 0.0f;

    const int abase = g4 * PLANE + wid * 72 + g2 + 3;
    const int a2off = 4 * PLANE;

    for (int t = 0; t < NCH; t++) {
        if (t + 1 < NCH) asm volatile("cp.async.wait_group 1;\n" ::);
        else             asm volatile("cp.async.wait_group 0;\n" ::);
        __syncthreads();
        if (t + 2 < NCH) { stageA(t + 2, (t + 2) % 3); cp_commit(); }

        const uint* sif = si_p + (t % 3) * SI_W;
        const uint* sbf = sw_p + t * CHUNK_W;

        uint ball[3][4][2];
#pragma unroll
        for (int q = 0; q < 3; q++)
#pragma unroll
            for (int nn = 0; nn < 4; nn++) {
                uint2 v = *reinterpret_cast<const uint2*>(
                    sbf + ((q * 4 + nn) * 32 + lane) * 2);
                ball[q][nn][0] = v.x;
                ball[q][nn][1] = v.y;
            }
#pragma unroll
        for (int q = 0; q < 3; q++) {
#pragma unroll
            for (int m = 0; m < 4; m++) {
                int ai = abase + q + m * 16;
                uint a0 = sif[ai];
                uint a1 = sif[ai + 8];
                uint a2 = sif[ai + a2off];
                uint a3 = sif[ai + a2off + 8];
#pragma unroll
                for (int nn = 0; nn < 4; nn++)
                    mma_f16(acc[m][nn], a0, a1, a2, a3,
                            ball[q][nn][0], ball[q][nn][1]);
            }
        }
    }

    if (FINAL) {
        float* out = (float*)outv;
        const int Cout = OCG * 32;
        const int h = h0 + wid;
#pragma unroll
        for (int m = 0; m < 4; m++) {
#pragma unroll
            for (int nn = 0; nn < 4; nn++) {
                int oc = ocg * 32 + nn * 8 + 2 * g4;
                int wv = w0 + m * 16 + g2;
                float* p0 = out + ((size_t)(n * Cout + oc) * H + h) * W + wv;
                float* p1 = p0 + (size_t)H * W;
                p0[0] = dlrelu(acc[m][nn][0]);
                p1[0] = dlrelu(acc[m][nn][1]);
                p0[8] = dlrelu(acc[m][nn][2]);
                p1[8] = dlrelu(acc[m][nn][3]);
            }
        }
    } else {
        uint* out = (uint*)outv;
        const int C2out = OCG * 16;
        const int h = h0 + wid;
#pragma unroll
        for (int m = 0; m < 4; m++) {
#pragma unroll
            for (int nn = 0; nn < 4; nn++) {
                int ocp = ocg * 16 + nn * 4 + g4;
                int wv  = w0 + m * 16 + g2;
                uint* p = out + ((size_t)(n * C2out + ocp) * H + h) * W + wv;
                p[0] = pack_h2(dlrelu(acc[m][nn][0]), dlrelu(acc[m][nn][1]));
                p[8] = pack_h2(dlrelu(acc[m][nn][2]), dlrelu(acc[m][nn][3]));
            }
        }
    }
}

// ---------------------------------------------------------------------------
extern "C" void kernel_launch(void* const* d_in, const int* in_sizes, int n_in,
                              void* d_out, int out_size)
{
    const float* x  = (const float*)d_in[0];
    const float* w1 = (const float*)d_in[1];
    const float* w2 = (const float*)d_in[2];
    const float* w3 = (const float*)d_in[3];
    const float* w4 = (const float*)d_in[4];
    const float* w5 = (const float*)d_in[5];
    const float* w6 = (const float*)d_in[6];

    uint *A, *B, *Wp;
    cudaGetSymbolAddress((void**)&A, g_bufA);
    cudaGetSymbolAddress((void**)&B, g_bufB);
    cudaGetSymbolAddress((void**)&Wp, g_bufW);

    const int o2 = 0, o3 = 4608, o4 = 13824, o5 = 32256, o6 = 44544;

    // Dynamic smem sizes (bytes)
    const int SM_C1 = (832 + 10240 + 512) * 4;     // 46336 (conv1 im2col)
    const int SM_C2 = (2 * 3392 + 2 * 2304) * 4;   // 45568 (CIN=32)
    const int SM_C4 = (2 * 3392 + 4 * 2304) * 4;   // 64000 (CIN=64)
    const int SM_O5 = (3 * 4672 + 4 * 768) * 4;    // 68352 (CIN=64 ONEROW)
    const int SM_O6 = (3 * 4672 + 8 * 768) * 4;    // 80640 (CIN=128 ONEROW)

    cudaFuncSetAttribute(conv3x3_s2<32, 1>,
                         cudaFuncAttributeMaxDynamicSharedMemorySize, SM_C2);
    cudaFuncSetAttribute(conv3x3_s2<32, 0>,
                         cudaFuncAttributeMaxDynamicSharedMemorySize, SM_C2);
    cudaFuncSetAttribute(conv3x3_s2<64, 1>,
                         cudaFuncAttributeMaxDynamicSharedMemorySize, SM_C4);
    cudaFuncSetAttribute(conv1x3_s3<64, 0>,
                         cudaFuncAttributeMaxDynamicSharedMemorySize, SM_O5);
    cudaFuncSetAttribute(conv1x3_s3<128, 1>,
                         cudaFuncAttributeMaxDynamicSharedMemorySize, SM_O6);

    // conv1 (im2col MMA, +folded weight pack): x -> A fp16 [2][16cp][1024][256]
    conv1_mma<<<dim3(4, 128, 2), 256, SM_C1>>>(x, w1, A, w2, w3, w4, w5, w6, Wp);

    // conv2 (+pool1 fused): A -> B fp16 [2][16cp][512][128]
    conv3x3_s2<32, 1><<<dim3(8, 128, 2), 256, SM_C2>>>(
        A, Wp + o2, B, 1024, 256, 512, 1);

    // conv3: B -> A fp16 [2][32cp][512][128] (sliceH=32)
    conv3x3_s2<32, 0><<<dim3(4, 64, 4), 256, SM_C2>>>(
        B, Wp + o3, A, 512, 128, 32, 2);

    // conv4 (+pool2 fused): A -> B fp16 [2][32cp][256][64]
    conv3x3_s2<64, 1><<<dim3(4, 64, 4), 256, SM_C4>>>(
        A, Wp + o4, B, 512, 128, 32, 2);

    // conv5: B -> A fp16 [2][64cp][256][64] (1x3 middle row)
    conv1x3_s3<64, 0><<<dim3(1, 32, 8), 256, SM_O5>>>(
        B, Wp + o5, A, 256, 64, 4);

    // conv6: A -> out fp32 NCHW [2,128,256,64] (final)
    conv1x3_s3<128, 1><<<dim3(1, 32, 8), 256, SM_O6>>>(
        A, Wp + o6, d_out, 256, 64, 4);
}